// round 13
// baseline (speedup 1.0000x reference)
#include <cuda_runtime.h>
#include <cuda_bf16.h>
#include <cuda_fp16.h>
#include <math.h>
#include <stdint.h>

#define SQ   128
#define UBN  256
#define HD   128
#define HH2  256
#define NLOC 8000
#define DEG  16

// ---------------- scratch (device globals; no allocation allowed) ----------
__device__ float g_encpre[NLOC*HD];
__device__ float g_encwIH[NLOC*HD];
__device__ float g_encwP [NLOC*HH2];
__device__ float g_Wcomb [HD*384];
__device__ float g_rbias [HD];
__device__ float g_pbias [HH2];
__device__ float g_rnn   [SQ*UBN*HD];
__device__ float g_pproj [UBN*HH2];
__device__ float g_pu    [UBN*HD];
__device__ float g_sim   [UBN*SQ];
__device__ float g_tT [UBN*SQ];
__device__ float g_sxT[UBN*SQ];
__device__ float g_syT[UBN*SQ];
__device__ float g_prebias[(size_t)UBN*NLOC];
__device__ __half g_Ah[(size_t)SQ*UBN*HD];   // fp16 A, u-major rows (u*SQ+i)
__device__ __half g_Bh[(size_t)NLOC*HD];     // fp16 B

extern __shared__ float sm[];

// ---------------- helpers ----------------------------------------------------
__device__ __forceinline__ uint32_t s2u(const void* p) {
    uint32_t a;
    asm("{ .reg .u64 t; cvta.to.shared.u64 t, %1; cvt.u32.u64 %0, t; }"
        : "=r"(a) : "l"(p));
    return a;
}
__device__ __forceinline__ void ldsm4(uint32_t& r0, uint32_t& r1,
                                      uint32_t& r2, uint32_t& r3, uint32_t addr) {
    asm volatile("ldmatrix.sync.aligned.m8n8.x4.shared.b16 {%0,%1,%2,%3}, [%4];"
                 : "=r"(r0), "=r"(r1), "=r"(r2), "=r"(r3) : "r"(addr));
}
__device__ __forceinline__ void mma_f16(float* d, const uint32_t* a,
                                        const uint32_t* b) {
    asm volatile(
        "mma.sync.aligned.m16n8k16.row.col.f32.f16.f16.f32 "
        "{%0,%1,%2,%3}, {%4,%5,%6,%7}, {%8,%9}, {%0,%1,%2,%3};"
        : "+f"(d[0]), "+f"(d[1]), "+f"(d[2]), "+f"(d[3])
        : "r"(a[0]), "r"(a[1]), "r"(a[2]), "r"(a[3]), "r"(b[0]), "r"(b[1]));
}
__device__ __forceinline__ void cpa16(uint32_t dst, const void* src) {
    asm volatile("cp.async.cg.shared.global [%0], [%1], 16;"
                 :: "r"(dst), "l"(src) : "memory");
}
__device__ __forceinline__ void cpa_commit() {
    asm volatile("cp.async.commit_group;" ::: "memory");
}
__device__ __forceinline__ void cpa_waitall() {
    asm volatile("cp.async.wait_group 0;" ::: "memory");
}
// smem byte offset for row-major [row][128 x 16-bit] with XOR-16B swizzle
__device__ __forceinline__ uint32_t swz(uint32_t row, uint32_t byte) {
    return row*256 + ((((byte >> 4) ^ (row & 7)) << 4) | (byte & 15));
}
__device__ __forceinline__ float ftanh(float x) {
    float e = __expf(2.f * x);
    return 1.f - 2.f / (e + 1.f);
}

// ---------------- K1: graph-conv gather -------------------------------------
__global__ void k_gconv_gather(const int* __restrict__ cols,
                               const float* __restrict__ vals,
                               const float* __restrict__ loc_emb) {
    int i = blockIdx.x, h = threadIdx.x;
    float acc = vals[NLOC*DEG + i] * loc_emb[i*HD + h];
    #pragma unroll
    for (int d = 0; d < DEG; d++) {
        int e = i*DEG + d;
        acc += vals[e] * loc_emb[cols[e]*HD + h];
    }
    g_encpre[i*HD + h] = acc;
}

// ---------------- K2a: Wcomb = Wg @ [W_ih | W_proj] -------------------------
__global__ void __launch_bounds__(384) k_combw(const float* __restrict__ Wg,
                                               const float* __restrict__ Wih,
                                               const float* __restrict__ Wp) {
    __shared__ float wg[HD];
    int k = blockIdx.x, c = threadIdx.x;
    if (c < HD) wg[c] = Wg[k*HD + c];
    __syncthreads();
    float acc = 0.f;
    if (c < HD) {
        for (int j = 0; j < HD; j++) acc += wg[j] * Wih[j*HD + c];
    } else {
        int c2 = c - HD;
        for (int j = 0; j < HD; j++) acc += wg[j] * Wp[j*HH2 + c2];
    }
    g_Wcomb[k*384 + c] = acc;
}

// ---------------- K2b: fold biases ------------------------------------------
__global__ void __launch_bounds__(384) k_bias(const float* __restrict__ bg,
                                              const float* __restrict__ Wih,
                                              const float* __restrict__ Wp,
                                              const float* __restrict__ b_ih,
                                              const float* __restrict__ b_hh,
                                              const float* __restrict__ bp) {
    __shared__ float sbg[HD];
    int c = threadIdx.x;
    if (c < HD) sbg[c] = bg[c];
    __syncthreads();
    if (c < HD) {
        float acc = b_ih[c] + b_hh[c];
        for (int j = 0; j < HD; j++) acc += sbg[j] * Wih[j*HD + c];
        g_rbias[c] = acc;
    } else {
        int c2 = c - HD;
        float acc = bp[c2];
        for (int j = 0; j < HD; j++) acc += sbg[j] * Wp[j*HH2 + c2];
        g_pbias[c2] = acc;
    }
}

// ---------------- K2c: fused table GEMM  encpre @ Wcomb ---------------------
__global__ void __launch_bounds__(384) k_tabfused() {
    __shared__ __align__(16) float at[128*36];   // at[k*36 + r]
    int r0 = blockIdx.x * 32, c = threadIdx.x;
    for (int q = c; q < 32*HD; q += 384) {
        int r = q >> 7, k = q & 127;
        at[k*36 + r] = g_encpre[(r0 + r)*HD + k];
    }
    float pbv = (c >= HD) ? g_pbias[c - HD] : 0.f;
    __syncthreads();
    float acc[32];
    #pragma unroll
    for (int r = 0; r < 32; r++) acc[r] = 0.f;
    #pragma unroll 4
    for (int k = 0; k < HD; k++) {
        float w = g_Wcomb[k*384 + c];
        #pragma unroll
        for (int rq = 0; rq < 8; rq++) {
            float4 av = *(const float4*)&at[k*36 + rq*4];
            acc[rq*4+0] += av.x * w;
            acc[rq*4+1] += av.y * w;
            acc[rq*4+2] += av.z * w;
            acc[rq*4+3] += av.w * w;
        }
    }
    if (c < HD) {
        for (int r = 0; r < 32; r++) g_encwIH[(r0 + r)*HD + c] = acc[r];
    } else {
        int c2 = c - HD;
        for (int r = 0; r < 32; r++)
            g_encwP[(size_t)(r0 + r)*HH2 + c2] = ftanh(acc[r] + pbv);
    }
}

// ---------------- K4: p_u + p_proj ------------------------------------------
__global__ void k_pproj(const int* __restrict__ au,
                        const float* __restrict__ user_emb,
                        const float* __restrict__ W_proj,
                        const float* __restrict__ b_proj) {
    __shared__ float pu[HD];
    int u = blockIdx.x, c = threadIdx.x;   // 256 threads
    if (c < HD) pu[c] = user_emb[au[u]*HD + c];
    __syncthreads();
    if (c < HD) g_pu[u*HD + c] = pu[c];
    float acc = b_proj[c];
    for (int k = 0; k < HD; k++) acc += pu[k] * W_proj[k*HH2 + c];
    g_pproj[u*HH2 + c] = ftanh(acc);
}

// ---------------- K5: RNN, W_hh in registers, 2 users / block ---------------
__global__ void __launch_bounds__(128) k_rnn2(const int* __restrict__ x,
                                              const float* __restrict__ W_hh,
                                              const float* __restrict__ h0) {
    __shared__ __align__(16) float hs0[HD];
    __shared__ __align__(16) float hs1[HD];
    __shared__ int sidx[2];
    int j = threadIdx.x;
    int u0 = blockIdx.x * 2;

    float wr[HD];
    #pragma unroll
    for (int k = 0; k < HD; k++) wr[k] = W_hh[k*HD + j];
    float bias = g_rbias[j];
    hs0[j] = h0[u0*HD + j];
    hs1[j] = h0[(u0 + 1)*HD + j];
    __syncthreads();

    for (int t = 0; t < SQ; t++) {
        if (j < 2) sidx[j] = x[t*UBN + u0 + j];
        __syncthreads();
        float a0 = g_encwIH[sidx[0]*HD + j] + bias;
        float a1 = g_encwIH[sidx[1]*HD + j] + bias;
        const float4* h40 = (const float4*)hs0;
        const float4* h41 = (const float4*)hs1;
        #pragma unroll
        for (int k4 = 0; k4 < HD/4; k4++) {
            float4 v0 = h40[k4], v1 = h41[k4];
            a0 += wr[4*k4+0]*v0.x + wr[4*k4+1]*v0.y
                + wr[4*k4+2]*v0.z + wr[4*k4+3]*v0.w;
            a1 += wr[4*k4+0]*v1.x + wr[4*k4+1]*v1.y
                + wr[4*k4+2]*v1.z + wr[4*k4+3]*v1.w;
        }
        float n0 = ftanh(a0);
        float n1 = ftanh(a1);
        __syncthreads();
        hs0[j] = n0;
        hs1[j] = n1;
        g_rnn[(t*UBN + u0)*HD + j]     = n0;
        g_rnn[(t*UBN + u0 + 1)*HD + j] = n1;
    }
}

// ---------------- K6: sim[u][s] via encwP gather -----------------------------
__global__ void __launch_bounds__(256) k_sim2(const int* __restrict__ x,
                                              const float* __restrict__ pref) {
    __shared__ __align__(16) float pc[HH2];
    int u = blockIdx.x, tid = threadIdx.x;
    pc[tid] = g_pproj[u*HH2 + tid] + pref[tid];
    __syncthreads();
    int w = tid >> 5, lane = tid & 31;
    for (int s = w; s < SQ; s += 8) {
        int loc = x[s*UBN + u];
        const float4* row = (const float4*)&g_encwP[(size_t)loc*HH2];
        float acc = 0.f;
        #pragma unroll
        for (int q = 0; q < 2; q++) {
            float4 v = row[lane*2 + q];
            float4 p = *(const float4*)&pc[lane*8 + q*4];
            float d0 = p.x - v.x, d1 = p.y - v.y, d2 = p.z - v.z, d3 = p.w - v.w;
            acc += d0*d0 + d1*d1 + d2*d2 + d3*d3;
        }
        #pragma unroll
        for (int o = 16; o > 0; o >>= 1) acc += __shfl_down_sync(0xffffffffu, acc, o);
        if (lane == 0) {
            float z = sqrtf(acc + 1e-12f);
            g_sim[u*SQ + s] = 1.f / (1.f + __expf(z));
        }
    }
}

// ---------------- K6b: transpose t/s into [U][S] float layout ----------------
__global__ void k_transp(const int* __restrict__ t, const int* __restrict__ s2) {
    __shared__ float T[3][32][33];
    int u0 = blockIdx.x * 32, s0 = blockIdx.y * 32;
    int tx = threadIdx.x, ty = threadIdx.y;
    int s = s0 + ty, u = u0 + tx;
    T[0][ty][tx] = (float)t[s*UBN + u];
    T[1][ty][tx] = (float)s2[(s*UBN + u)*2 + 0];
    T[2][ty][tx] = (float)s2[(s*UBN + u)*2 + 1];
    __syncthreads();
    int uo = u0 + ty, so = s0 + tx;
    g_tT [uo*SQ + so] = T[0][tx][ty];
    g_sxT[uo*SQ + so] = T[1][tx][ty];
    g_syT[uo*SQ + so] = T[2][tx][ty];
}

// ---------------- K8: fused weights + weighted sum -> fp16 A ----------------
__global__ void __launch_bounds__(128) k_wsum() {
    __shared__ __align__(16) float wsm[8*SQ];   // w[q][j]
    __shared__ float ssum[8];
    const float K1 = 7.2722052166430399e-05f;   // 2*pi/86400
    const float K2 = 1.1574074074074074e-06f;   // 0.1/86400
    int u = blockIdx.x, ig = blockIdx.y, h = threadIdx.x;
    int ibase = ig * 8;

    const float* tT  = &g_tT [u*SQ];
    const float* sxT = &g_sxT[u*SQ];
    const float* syT = &g_syT[u*SQ];
    const float* sim = &g_sim[u*SQ];

    #pragma unroll
    for (int q8 = 0; q8 < 8; q8++) {
        int idx = q8*128 + h;                 // 0..1023
        int q = idx >> 7, j = idx & 127;
        int i = ibase + q;
        float w = 0.f;
        if (j <= i) {
            float dt = tT[i] - tT[j];
            float dx = sxT[i] - sxT[j];
            float dy = syT[i] - syT[j];
            float ds = sqrtf(dx*dx + dy*dy);
            float a  = (__cosf(dt * K1) + 1.f) * 0.5f * __expf(-dt * K2);
            float b  = __expf(-ds * 0.1f);
            w = (a*b + 1e-10f) * sim[j];
        }
        wsm[idx] = w;
    }
    __syncthreads();
    {
        int wp = h >> 5, lane = h & 31;
        #pragma unroll
        for (int rr = 0; rr < 2; rr++) {
            int q = wp + rr*4;
            float v = wsm[q*SQ + lane] + wsm[q*SQ + lane + 32]
                    + wsm[q*SQ + lane + 64] + wsm[q*SQ + lane + 96];
            #pragma unroll
            for (int o = 16; o > 0; o >>= 1) v += __shfl_down_sync(0xffffffffu, v, o);
            if (lane == 0) ssum[q] = v;
        }
    }
    __syncthreads();

    float acc[8];
    #pragma unroll
    for (int q = 0; q < 8; q++) acc[q] = 0.f;
    int jmax = ibase + 8;
    for (int j = 0; j < jmax; j++) {
        float r = g_rnn[(j*UBN + u)*HD + h];
        #pragma unroll
        for (int q = 0; q < 8; q++) acc[q] += wsm[q*SQ + j] * r;
    }
    #pragma unroll
    for (int q = 0; q < 8; q++) {
        int m = u*SQ + ibase + q;                 // u-major row
        g_Ah[(size_t)m*HD + h] = __float2half_rn(acc[q] / ssum[q]);
    }
}

// ---------------- K9a: pack/transpose Wfc top half -> fp16 ------------------
__global__ void k_packB(const float* __restrict__ Wfc) {
    __shared__ float t[32][33];
    int nx = blockIdx.x*32, ky = blockIdx.y*32;
    int tx = threadIdx.x, ty = threadIdx.y;
    t[ty][tx] = Wfc[(size_t)(ky + ty)*NLOC + nx + tx];
    __syncthreads();
    int n = nx + ty, k = ky + tx;
    g_Bh[(size_t)n*HD + k] = __float2half_rn(t[tx][ty]);
}

// ---------------- K9b: prebias[u][n] = p_u @ Wfc_bot + b_fc -----------------
__global__ void __launch_bounds__(256) k_prebias(const float* __restrict__ Wfc,
                                                 const float* __restrict__ bfc) {
    __shared__ float spu[256*32];
    int tid = threadIdx.x;
    int n = blockIdx.x*64 + (tid & 63);
    int ug = tid >> 6;
    float acc[64];
    #pragma unroll
    for (int i = 0; i < 64; i++) acc[i] = 0.f;
    for (int k0 = 0; k0 < HD; k0 += 32) {
        __syncthreads();
        for (int q = tid; q < 256*32; q += 256)
            spu[q] = g_pu[(q >> 5)*HD + k0 + (q & 31)];
        __syncthreads();
        #pragma unroll
        for (int kk = 0; kk < 32; kk++) {
            float w = Wfc[(size_t)(HD + k0 + kk)*NLOC + n];
            #pragma unroll
            for (int uu = 0; uu < 64; uu++)
                acc[uu] += spu[(ug*64 + uu)*32 + kk] * w;
        }
    }
    float b = bfc[n];
    #pragma unroll
    for (int uu = 0; uu < 64; uu++)
        g_prebias[(size_t)(ug*64 + uu)*NLOC + n] = acc[uu] + b;
}

// ---------------- K10: persistent single-wave pipelined fp16 GEMM -----------
// grid (9, 128): CTA owns m-tile (256 rows, u-major), iterates 7 n-tiles.
// smem: A 64KB | B[2] 2x32KB | prebias[2] 2x2KB = 136KB total
#define FCA_OFF  0
#define FCB_OFF  65536
#define FCPB_OFF 131072
#define FC_SMEM  135168
#define NT_PER   7

__global__ void __launch_bounds__(512, 1) k_fc_mma(float* __restrict__ out) {
    char* smc = (char*)sm;
    uint32_t smb = s2u(smc);
    int tid = threadIdx.x, wid = tid >> 5, lane = tid & 31;
    int ngrp = blockIdx.x;                 // 0..8
    int m0 = blockIdx.y * 256;             // rows u-major: u = row>>7
    int u0 = m0 >> 7;
    int warpM = (wid >> 2) * 64;
    int warpN = (wid & 3) * 32;

    // ---- async load A once (64KB) ----
    {
        const uint4* src = (const uint4*)g_Ah;
        #pragma unroll
        for (int it = 0; it < 8; it++) {
            int q = it*512 + tid;
            int rowg = q >> 4, c16 = q & 15;
            cpa16(smb + FCA_OFF + swz(rowg, c16*16),
                  &src[(size_t)(m0 + rowg)*16 + c16]);
        }
    }
    // ---- B/prebias loader (into buffer buf for column tile n0) ----
    auto loadB = [&](int buf, int n0) {
        const uint4* src = (const uint4*)g_Bh;
        #pragma unroll
        for (int it = 0; it < 4; it++) {
            int q = it*512 + tid;
            int rowg = q >> 4, c16 = q & 15;
            uint32_t d0 = smb + FCB_OFF + buf*32768 + swz(rowg, c16*16);
            if (n0 + rowg < NLOC) {
                cpa16(d0, &src[(size_t)(n0 + rowg)*16 + c16]);
            } else {
                uint4 z = make_uint4(0u, 0u, 0u, 0u);
                *(uint4*)(smc + (d0 - smb)) = z;
            }
        }
        if (tid < 64) {
            int user = tid >> 5, c4 = (tid & 31) * 4;
            int col = n0 + c4;
            uint32_t dst = smb + FCPB_OFF + buf*2048 + user*512 + c4*4;
            if (col < NLOC) {
                cpa16(dst, &g_prebias[(size_t)(u0 + user)*NLOC + col]);
            } else {
                uint4 z = make_uint4(0u, 0u, 0u, 0u);
                *(uint4*)(smc + (dst - smb)) = z;
            }
        }
    };

    loadB(0, ngrp*NT_PER*128);
    cpa_commit();
    cpa_waitall();
    __syncthreads();

    uint32_t aRow = warpM + (lane & 15);
    uint32_t aByt = (lane >> 4) * 16;
    uint32_t bRow = warpN + ((lane >> 4) << 3) + (lane & 7);
    uint32_t bByt = ((lane >> 3) & 1) << 4;
    uint32_t aPl = smb + FCA_OFF;

    for (int itile = 0; itile < NT_PER; itile++) {
        int n0 = (ngrp*NT_PER + itile) * 128;
        // prefetch next B/prebias into the other buffer
        if (itile + 1 < NT_PER) {
            loadB((itile + 1) & 1, n0 + 128);
            cpa_commit();
        }
        uint32_t bPl = smb + FCB_OFF + (itile & 1)*32768;

        float acc[4][4][4];
        #pragma unroll
        for (int i = 0; i < 4; i++)
            #pragma unroll
            for (int j = 0; j < 4; j++)
                #pragma unroll
                for (int q = 0; q < 4; q++) acc[i][j][q] = 0.f;

        #pragma unroll
        for (int kk = 0; kk < 8; kk++) {
            uint32_t bb[8];
            ldsm4(bb[0], bb[1], bb[2], bb[3], bPl + swz(bRow,      kk*32 + bByt));
            ldsm4(bb[4], bb[5], bb[6], bb[7], bPl + swz(bRow + 16, kk*32 + bByt));
            #pragma unroll
            for (int mt = 0; mt < 4; mt++) {
                uint32_t a[4];
                ldsm4(a[0], a[1], a[2], a[3], aPl + swz(aRow + mt*16, kk*32 + aByt));
                #pragma unroll
                for (int nt = 0; nt < 4; nt++) mma_f16(acc[mt][nt], a, &bb[nt*2]);
            }
        }

        // epilogue: decode (u, i), add staged prebias, write out
        const float* pb = (const float*)(smc + FCPB_OFF + (itile & 1)*2048);
        #pragma unroll
        for (int mt = 0; mt < 4; mt++) {
            int moff = warpM + mt*16 + (lane >> 2);
            int ul = moff >> 7;
            int i  = moff & 127;
            size_t row0 = (size_t)(i*UBN + u0 + ul)*NLOC;
            size_t row1 = (size_t)((i + 8)*UBN + u0 + ul)*NLOC;
            #pragma unroll
            for (int nt = 0; nt < 4; nt++) {
                int cloc = warpN + nt*8 + (lane & 3)*2;
                int col  = n0 + cloc;
                if (col < NLOC) {
                    float2 pbv = *(const float2*)&pb[(ul << 7) + cloc];
                    float2 v0 = make_float2(acc[mt][nt][0] + pbv.x, acc[mt][nt][1] + pbv.y);
                    float2 v1 = make_float2(acc[mt][nt][2] + pbv.x, acc[mt][nt][3] + pbv.y);
                    *(float2*)&out[row0 + col] = v0;
                    *(float2*)&out[row1 + col] = v1;
                }
            }
        }

        if (itile + 1 < NT_PER) {
            cpa_waitall();
            __syncthreads();
        }
    }
}

// ---------------- K11: append h_last -----------------------------------------
__global__ void k_hlast(float* __restrict__ out) {
    int idx = blockIdx.x * 256 + threadIdx.x;            // 0..32767
    out[(size_t)SQ*UBN*NLOC + idx] = g_rnn[(size_t)(SQ-1)*UBN*HD + idx];
}

// ---------------- launch ------------------------------------------------------
extern "C" void kernel_launch(void* const* d_in, const int* in_sizes, int n_in,
                              void* d_out, int out_size) {
    const int*   x        = (const int*)  d_in[0];
    const int*   t        = (const int*)  d_in[1];
    const int*   s2       = (const int*)  d_in[3];
    const float* h0       = (const float*)d_in[7];
    const int*   au       = (const int*)  d_in[8];
    const int*   ecols    = (const int*)  d_in[10];
    const float* evals    = (const float*)d_in[11];
    const float* loc_emb  = (const float*)d_in[12];
    const float* user_emb = (const float*)d_in[13];
    const float* pref     = (const float*)d_in[14];
    const float* W_proj   = (const float*)d_in[15];
    const float* b_proj   = (const float*)d_in[16];
    const float* W_gconv  = (const float*)d_in[17];
    const float* b_gconv  = (const float*)d_in[18];
    const float* W_ih     = (const float*)d_in[19];
    const float* W_hh     = (const float*)d_in[20];
    const float* b_ih     = (const float*)d_in[21];
    const float* b_hh     = (const float*)d_in[22];
    const float* W_fc     = (const float*)d_in[23];
    const float* b_fc     = (const float*)d_in[24];
    float* out = (float*)d_out;

    cudaFuncSetAttribute(k_fc_mma, cudaFuncAttributeMaxDynamicSharedMemorySize, FC_SMEM);

    k_gconv_gather<<<NLOC, HD>>>(ecols, evals, loc_emb);
    k_combw<<<HD, 384>>>(W_gconv, W_ih, W_proj);
    k_bias<<<1, 384>>>(b_gconv, W_ih, W_proj, b_ih, b_hh, b_proj);
    k_packB<<<dim3(NLOC/32, HD/32), dim3(32, 32)>>>(W_fc);
    k_pproj<<<UBN, HH2>>>(au, user_emb, W_proj, b_proj);
    k_prebias<<<NLOC/64, 256>>>(W_fc, b_fc);
    k_transp<<<dim3(UBN/32, SQ/32), dim3(32, 32)>>>(t, s2);
    k_tabfused<<<NLOC/32, 384>>>();
    k_rnn2<<<UBN/2, HD>>>(x, W_hh, h0);
    k_sim2<<<UBN, 256>>>(x, pref);
    k_wsum<<<dim3(UBN, SQ/8), HD>>>();
    k_fc_mma<<<dim3(9, SQ*UBN/256), 512, FC_SMEM>>>(out);
    k_hlast<<<128, 256>>>(out);
}

// round 14
// speedup vs baseline: 1.0651x; 1.0651x over previous
#include <cuda_runtime.h>
#include <cuda_bf16.h>
#include <cuda_fp16.h>
#include <math.h>
#include <stdint.h>

#define SQ   128
#define UBN  256
#define HD   128
#define HH2  256
#define NLOC 8000
#define DEG  16

// ---------------- scratch (device globals; no allocation allowed) ----------
__device__ float g_encpre[NLOC*HD];
__device__ float g_encwIH[NLOC*HD];
__device__ float g_encwP [NLOC*HH2];
__device__ float g_Wcomb [HD*384];
__device__ float g_rbias [HD];
__device__ float g_pbias [HH2];
__device__ float g_rnn   [SQ*UBN*HD];
__device__ float g_pproj [UBN*HH2];
__device__ float g_pu    [UBN*HD];
__device__ float g_sim   [UBN*SQ];
__device__ float g_tT [UBN*SQ];
__device__ float g_sxT[UBN*SQ];
__device__ float g_syT[UBN*SQ];
__device__ float g_prebias[(size_t)UBN*NLOC];
__device__ __half g_Ah[(size_t)SQ*UBN*HD];   // fp16 A, u-major rows (u*SQ+i)
__device__ __half g_Bh[(size_t)NLOC*HD];     // fp16 B

extern __shared__ float sm[];

// ---------------- helpers ----------------------------------------------------
__device__ __forceinline__ uint32_t s2u(const void* p) {
    uint32_t a;
    asm("{ .reg .u64 t; cvta.to.shared.u64 t, %1; cvt.u32.u64 %0, t; }"
        : "=r"(a) : "l"(p));
    return a;
}
__device__ __forceinline__ void ldsm4(uint32_t& r0, uint32_t& r1,
                                      uint32_t& r2, uint32_t& r3, uint32_t addr) {
    asm volatile("ldmatrix.sync.aligned.m8n8.x4.shared.b16 {%0,%1,%2,%3}, [%4];"
                 : "=r"(r0), "=r"(r1), "=r"(r2), "=r"(r3) : "r"(addr));
}
__device__ __forceinline__ void mma_f16(float* d, const uint32_t* a,
                                        const uint32_t* b) {
    asm volatile(
        "mma.sync.aligned.m16n8k16.row.col.f32.f16.f16.f32 "
        "{%0,%1,%2,%3}, {%4,%5,%6,%7}, {%8,%9}, {%0,%1,%2,%3};"
        : "+f"(d[0]), "+f"(d[1]), "+f"(d[2]), "+f"(d[3])
        : "r"(a[0]), "r"(a[1]), "r"(a[2]), "r"(a[3]), "r"(b[0]), "r"(b[1]));
}
__device__ __forceinline__ void cpa16(uint32_t dst, const void* src) {
    asm volatile("cp.async.cg.shared.global [%0], [%1], 16;"
                 :: "r"(dst), "l"(src) : "memory");
}
__device__ __forceinline__ void cpa_wait() {
    asm volatile("cp.async.commit_group;" ::: "memory");
    asm volatile("cp.async.wait_group 0;" ::: "memory");
}
// smem byte offset for row-major [row][128 x 16-bit] with XOR-16B swizzle
__device__ __forceinline__ uint32_t swz(uint32_t row, uint32_t byte) {
    return row*256 + ((((byte >> 4) ^ (row & 7)) << 4) | (byte & 15));
}
__device__ __forceinline__ float ftanh(float x) {
    float e = __expf(2.f * x);
    return 1.f - 2.f / (e + 1.f);
}

// ---------------- K1 (fused): gather | combw | bias --------------------------
// blocks [0, 2667): gconv gather, 3 loc rows each (384 thr = 3 x 128)
// blocks [2667, 2795): Wcomb row k = b - 2667
// block  2795: bias fold
#define GB_GATHER 2667
__global__ void __launch_bounds__(384) k_init(const int* __restrict__ cols,
                                              const float* __restrict__ vals,
                                              const float* __restrict__ loc_emb,
                                              const float* __restrict__ Wg,
                                              const float* __restrict__ Wih,
                                              const float* __restrict__ Wp,
                                              const float* __restrict__ bg,
                                              const float* __restrict__ b_ih,
                                              const float* __restrict__ b_hh,
                                              const float* __restrict__ bp) {
    int b = blockIdx.x, c = threadIdx.x;
    if (b < GB_GATHER) {
        int i = b*3 + (c >> 7);
        if (i < NLOC) {
            int h = c & 127;
            float acc = vals[NLOC*DEG + i] * loc_emb[i*HD + h];
            #pragma unroll
            for (int d = 0; d < DEG; d++) {
                int e = i*DEG + d;
                acc += vals[e] * loc_emb[cols[e]*HD + h];
            }
            g_encpre[i*HD + h] = acc;
        }
    } else if (b < GB_GATHER + HD) {
        __shared__ float wg[HD];
        int k = b - GB_GATHER;
        if (c < HD) wg[c] = Wg[k*HD + c];
        __syncthreads();
        float acc = 0.f;
        if (c < HD) {
            for (int j = 0; j < HD; j++) acc += wg[j] * Wih[j*HD + c];
        } else {
            int c2 = c - HD;
            for (int j = 0; j < HD; j++) acc += wg[j] * Wp[j*HH2 + c2];
        }
        g_Wcomb[k*384 + c] = acc;
    } else {
        __shared__ float sbg[HD];
        if (c < HD) sbg[c] = bg[c];
        __syncthreads();
        if (c < HD) {
            float acc = b_ih[c] + b_hh[c];
            for (int j = 0; j < HD; j++) acc += sbg[j] * Wih[j*HD + c];
            g_rbias[c] = acc;
        } else {
            int c2 = c - HD;
            float acc = bp[c2];
            for (int j = 0; j < HD; j++) acc += sbg[j] * Wp[j*HH2 + c2];
            g_pbias[c2] = acc;
        }
    }
}

// ---------------- K2c: fused table GEMM  encpre @ Wcomb ---------------------
__global__ void __launch_bounds__(384) k_tabfused() {
    __shared__ __align__(16) float at[128*36];   // at[k*36 + r]
    int r0 = blockIdx.x * 32, c = threadIdx.x;
    for (int q = c; q < 32*HD; q += 384) {
        int r = q >> 7, k = q & 127;
        at[k*36 + r] = g_encpre[(r0 + r)*HD + k];
    }
    float pbv = (c >= HD) ? g_pbias[c - HD] : 0.f;
    __syncthreads();
    float acc[32];
    #pragma unroll
    for (int r = 0; r < 32; r++) acc[r] = 0.f;
    #pragma unroll 4
    for (int k = 0; k < HD; k++) {
        float w = g_Wcomb[k*384 + c];
        #pragma unroll
        for (int rq = 0; rq < 8; rq++) {
            float4 av = *(const float4*)&at[k*36 + rq*4];
            acc[rq*4+0] += av.x * w;
            acc[rq*4+1] += av.y * w;
            acc[rq*4+2] += av.z * w;
            acc[rq*4+3] += av.w * w;
        }
    }
    if (c < HD) {
        for (int r = 0; r < 32; r++) g_encwIH[(r0 + r)*HD + c] = acc[r];
    } else {
        int c2 = c - HD;
        for (int r = 0; r < 32; r++)
            g_encwP[(size_t)(r0 + r)*HH2 + c2] = ftanh(acc[r] + pbv);
    }
}

// ---------------- K4: p_u + p_proj ------------------------------------------
__global__ void k_pproj(const int* __restrict__ au,
                        const float* __restrict__ user_emb,
                        const float* __restrict__ W_proj,
                        const float* __restrict__ b_proj) {
    __shared__ float pu[HD];
    int u = blockIdx.x, c = threadIdx.x;   // 256 threads
    if (c < HD) pu[c] = user_emb[au[u]*HD + c];
    __syncthreads();
    if (c < HD) g_pu[u*HD + c] = pu[c];
    float acc = b_proj[c];
    for (int k = 0; k < HD; k++) acc += pu[k] * W_proj[k*HH2 + c];
    g_pproj[u*HH2 + c] = ftanh(acc);
}

// ---------------- K5: RNN (+h_last directly to out tail) --------------------
__global__ void __launch_bounds__(128) k_rnn2(const int* __restrict__ x,
                                              const float* __restrict__ W_hh,
                                              const float* __restrict__ h0,
                                              float* __restrict__ out) {
    __shared__ __align__(16) float hs0[HD];
    __shared__ __align__(16) float hs1[HD];
    __shared__ int sidx[2];
    int j = threadIdx.x;
    int u0 = blockIdx.x * 2;

    float wr[HD];
    #pragma unroll
    for (int k = 0; k < HD; k++) wr[k] = W_hh[k*HD + j];
    float bias = g_rbias[j];
    hs0[j] = h0[u0*HD + j];
    hs1[j] = h0[(u0 + 1)*HD + j];
    __syncthreads();

    for (int t = 0; t < SQ; t++) {
        if (j < 2) sidx[j] = x[t*UBN + u0 + j];
        __syncthreads();
        float a0 = g_encwIH[sidx[0]*HD + j] + bias;
        float a1 = g_encwIH[sidx[1]*HD + j] + bias;
        const float4* h40 = (const float4*)hs0;
        const float4* h41 = (const float4*)hs1;
        #pragma unroll
        for (int k4 = 0; k4 < HD/4; k4++) {
            float4 v0 = h40[k4], v1 = h41[k4];
            a0 += wr[4*k4+0]*v0.x + wr[4*k4+1]*v0.y
                + wr[4*k4+2]*v0.z + wr[4*k4+3]*v0.w;
            a1 += wr[4*k4+0]*v1.x + wr[4*k4+1]*v1.y
                + wr[4*k4+2]*v1.z + wr[4*k4+3]*v1.w;
        }
        float n0 = ftanh(a0);
        float n1 = ftanh(a1);
        __syncthreads();
        hs0[j] = n0;
        hs1[j] = n1;
        g_rnn[(t*UBN + u0)*HD + j]     = n0;
        g_rnn[(t*UBN + u0 + 1)*HD + j] = n1;
    }
    // h_last -> out tail (layout [1][UBN][HD])
    size_t base = (size_t)SQ*UBN*NLOC;
    out[base + (size_t)u0*HD + j]       = hs0[j];
    out[base + (size_t)(u0 + 1)*HD + j] = hs1[j];
}

// ---------------- K6: sim[u][s] via encwP gather -----------------------------
__global__ void __launch_bounds__(256) k_sim2(const int* __restrict__ x,
                                              const float* __restrict__ pref) {
    __shared__ __align__(16) float pc[HH2];
    int u = blockIdx.x, tid = threadIdx.x;
    pc[tid] = g_pproj[u*HH2 + tid] + pref[tid];
    __syncthreads();
    int w = tid >> 5, lane = tid & 31;
    for (int s = w; s < SQ; s += 8) {
        int loc = x[s*UBN + u];
        const float4* row = (const float4*)&g_encwP[(size_t)loc*HH2];
        float acc = 0.f;
        #pragma unroll
        for (int q = 0; q < 2; q++) {
            float4 v = row[lane*2 + q];
            float4 p = *(const float4*)&pc[lane*8 + q*4];
            float d0 = p.x - v.x, d1 = p.y - v.y, d2 = p.z - v.z, d3 = p.w - v.w;
            acc += d0*d0 + d1*d1 + d2*d2 + d3*d3;
        }
        #pragma unroll
        for (int o = 16; o > 0; o >>= 1) acc += __shfl_down_sync(0xffffffffu, acc, o);
        if (lane == 0) {
            float z = sqrtf(acc + 1e-12f);
            g_sim[u*SQ + s] = 1.f / (1.f + __expf(z));
        }
    }
}

// ---------------- K6b: transpose t/s into [U][S] float layout ----------------
__global__ void k_transp(const int* __restrict__ t, const int* __restrict__ s2) {
    __shared__ float T[3][32][33];
    int u0 = blockIdx.x * 32, s0 = blockIdx.y * 32;
    int tx = threadIdx.x, ty = threadIdx.y;
    int s = s0 + ty, u = u0 + tx;
    T[0][ty][tx] = (float)t[s*UBN + u];
    T[1][ty][tx] = (float)s2[(s*UBN + u)*2 + 0];
    T[2][ty][tx] = (float)s2[(s*UBN + u)*2 + 1];
    __syncthreads();
    int uo = u0 + ty, so = s0 + tx;
    g_tT [uo*SQ + so] = T[0][tx][ty];
    g_sxT[uo*SQ + so] = T[1][tx][ty];
    g_syT[uo*SQ + so] = T[2][tx][ty];
}

// ---------------- K8: fused weights + weighted sum -> fp16 A ----------------
__global__ void __launch_bounds__(128) k_wsum() {
    __shared__ __align__(16) float wsm[8*SQ];   // w[q][j]
    __shared__ float ssum[8];
    const float K1 = 7.2722052166430399e-05f;   // 2*pi/86400
    const float K2 = 1.1574074074074074e-06f;   // 0.1/86400
    int u = blockIdx.x, ig = blockIdx.y, h = threadIdx.x;
    int ibase = ig * 8;

    const float* tT  = &g_tT [u*SQ];
    const float* sxT = &g_sxT[u*SQ];
    const float* syT = &g_syT[u*SQ];
    const float* sim = &g_sim[u*SQ];

    #pragma unroll
    for (int q8 = 0; q8 < 8; q8++) {
        int idx = q8*128 + h;
        int q = idx >> 7, j = idx & 127;
        int i = ibase + q;
        float w = 0.f;
        if (j <= i) {
            float dt = tT[i] - tT[j];
            float dx = sxT[i] - sxT[j];
            float dy = syT[i] - syT[j];
            float ds = sqrtf(dx*dx + dy*dy);
            float a  = (__cosf(dt * K1) + 1.f) * 0.5f * __expf(-dt * K2);
            float b  = __expf(-ds * 0.1f);
            w = (a*b + 1e-10f) * sim[j];
        }
        wsm[idx] = w;
    }
    __syncthreads();
    {
        int wp = h >> 5, lane = h & 31;
        #pragma unroll
        for (int rr = 0; rr < 2; rr++) {
            int q = wp + rr*4;
            float v = wsm[q*SQ + lane] + wsm[q*SQ + lane + 32]
                    + wsm[q*SQ + lane + 64] + wsm[q*SQ + lane + 96];
            #pragma unroll
            for (int o = 16; o > 0; o >>= 1) v += __shfl_down_sync(0xffffffffu, v, o);
            if (lane == 0) ssum[q] = v;
        }
    }
    __syncthreads();

    float acc[8];
    #pragma unroll
    for (int q = 0; q < 8; q++) acc[q] = 0.f;
    int jmax = ibase + 8;
    for (int j = 0; j < jmax; j++) {
        float r = g_rnn[(j*UBN + u)*HD + h];
        #pragma unroll
        for (int q = 0; q < 8; q++) acc[q] += wsm[q*SQ + j] * r;
    }
    #pragma unroll
    for (int q = 0; q < 8; q++) {
        int m = u*SQ + ibase + q;                 // u-major row
        g_Ah[(size_t)m*HD + h] = __float2half_rn(acc[q] / ssum[q]);
    }
}

// ---------------- K9a: pack/transpose Wfc top half -> fp16 ------------------
__global__ void k_packB(const float* __restrict__ Wfc) {
    __shared__ float t[32][33];
    int nx = blockIdx.x*32, ky = blockIdx.y*32;
    int tx = threadIdx.x, ty = threadIdx.y;
    t[ty][tx] = Wfc[(size_t)(ky + ty)*NLOC + nx + tx];
    __syncthreads();
    int n = nx + ty, k = ky + tx;
    g_Bh[(size_t)n*HD + k] = __float2half_rn(t[tx][ty]);
}

// ---------------- K9b: prebias[u][n] = p_u @ Wfc_bot + b_fc -----------------
__global__ void __launch_bounds__(256) k_prebias(const float* __restrict__ Wfc,
                                                 const float* __restrict__ bfc) {
    __shared__ float spu[256*32];
    int tid = threadIdx.x;
    int n = blockIdx.x*64 + (tid & 63);
    int ug = tid >> 6;
    float acc[64];
    #pragma unroll
    for (int i = 0; i < 64; i++) acc[i] = 0.f;
    for (int k0 = 0; k0 < HD; k0 += 32) {
        __syncthreads();
        for (int q = tid; q < 256*32; q += 256)
            spu[q] = g_pu[(q >> 5)*HD + k0 + (q & 31)];
        __syncthreads();
        #pragma unroll
        for (int kk = 0; kk < 32; kk++) {
            float w = Wfc[(size_t)(HD + k0 + kk)*NLOC + n];
            #pragma unroll
            for (int uu = 0; uu < 64; uu++)
                acc[uu] += spu[(ug*64 + uu)*32 + kk] * w;
        }
    }
    float b = bfc[n];
    #pragma unroll
    for (int uu = 0; uu < 64; uu++)
        g_prebias[(size_t)(ug*64 + uu)*NLOC + n] = acc[uu] + b;
}

// ---------------- K10: single-group fp16 mma GEMM (round-11 proven) ---------
// Mtile=256 (u-major), Ntile=128. smem: A 64KB | B 32KB | prebias 1KB = 97KB
#define FCA_OFF  0
#define FCB_OFF  65536
#define FCPB_OFF 98304
#define FC_SMEM  99328

__global__ void __launch_bounds__(512, 1) k_fc_mma(float* __restrict__ out) {
    char* smc = (char*)sm;
    uint32_t smb = s2u(smc);
    int tid = threadIdx.x, wid = tid >> 5, lane = tid & 31;
    int n0 = blockIdx.x * 128;
    int m0 = blockIdx.y * 256;            // rows u-major: u = row>>7
    int u0 = m0 >> 7;
    int warpM = (wid >> 2) * 64;
    int warpN = (wid & 3) * 32;

    float acc[4][4][4];
    #pragma unroll
    for (int i = 0; i < 4; i++)
        #pragma unroll
        for (int j = 0; j < 4; j++)
            #pragma unroll
            for (int q = 0; q < 4; q++) acc[i][j][q] = 0.f;

    // ---- async load A (64KB) ----
    {
        const uint4* src = (const uint4*)g_Ah;
        #pragma unroll
        for (int it = 0; it < 8; it++) {
            int q = it*512 + tid;
            int rowg = q >> 4, c16 = q & 15;
            cpa16(smb + FCA_OFF + swz(rowg, c16*16),
                  &src[(size_t)(m0 + rowg)*16 + c16]);
        }
    }
    // ---- async load B (32KB), zero-fill OOB ----
    {
        const uint4* src = (const uint4*)g_Bh;
        #pragma unroll
        for (int it = 0; it < 4; it++) {
            int q = it*512 + tid;
            int rowg = q >> 4, c16 = q & 15;
            uint32_t d0 = smb + FCB_OFF + swz(rowg, c16*16);
            if (n0 + rowg < NLOC) {
                cpa16(d0, &src[(size_t)(n0 + rowg)*16 + c16]);
            } else {
                uint4 z = make_uint4(0u, 0u, 0u, 0u);
                *(uint4*)(smc + (d0 - smb)) = z;
            }
        }
    }
    // ---- stage prebias for 2 users x 128 cols ----
    {
        float* pb = (float*)(smc + FCPB_OFF);
        if (tid < 256) {
            int col = n0 + (tid & 127);
            float v = 0.f;
            if (col < NLOC) v = g_prebias[(size_t)(u0 + (tid >> 7))*NLOC + col];
            pb[tid] = v;
        }
    }
    cpa_wait();
    __syncthreads();

    uint32_t aRow = warpM + (lane & 15);
    uint32_t aByt = (lane >> 4) * 16;
    uint32_t bRow = warpN + ((lane >> 4) << 3) + (lane & 7);
    uint32_t bByt = ((lane >> 3) & 1) << 4;

    uint32_t aPl = smb + FCA_OFF;
    uint32_t bPl = smb + FCB_OFF;

    #pragma unroll
    for (int kk = 0; kk < 8; kk++) {
        uint32_t bb[8];
        ldsm4(bb[0], bb[1], bb[2], bb[3], bPl + swz(bRow,      kk*32 + bByt));
        ldsm4(bb[4], bb[5], bb[6], bb[7], bPl + swz(bRow + 16, kk*32 + bByt));
        #pragma unroll
        for (int mt = 0; mt < 4; mt++) {
            uint32_t a[4];
            ldsm4(a[0], a[1], a[2], a[3], aPl + swz(aRow + mt*16, kk*32 + aByt));
            #pragma unroll
            for (int nt = 0; nt < 4; nt++) mma_f16(acc[mt][nt], a, &bb[nt*2]);
        }
    }

    // ---- epilogue: decode (u, i), add staged prebias, write out ----
    const float* pb = (const float*)(smc + FCPB_OFF);
    #pragma unroll
    for (int mt = 0; mt < 4; mt++) {
        int moff = warpM + mt*16 + (lane >> 2);
        int ul = moff >> 7;
        int i  = moff & 127;
        size_t row0 = (size_t)(i*UBN + u0 + ul)*NLOC;
        size_t row1 = (size_t)((i + 8)*UBN + u0 + ul)*NLOC;
        #pragma unroll
        for (int nt = 0; nt < 4; nt++) {
            int cloc = warpN + nt*8 + (lane & 3)*2;
            int col  = n0 + cloc;
            if (col < NLOC) {
                float2 pbv = *(const float2*)&pb[(ul << 7) + cloc];
                float2 v0 = make_float2(acc[mt][nt][0] + pbv.x, acc[mt][nt][1] + pbv.y);
                float2 v1 = make_float2(acc[mt][nt][2] + pbv.x, acc[mt][nt][3] + pbv.y);
                *(float2*)&out[row0 + col] = v0;
                *(float2*)&out[row1 + col] = v1;
            }
        }
    }
}

// ---------------- launch ------------------------------------------------------
extern "C" void kernel_launch(void* const* d_in, const int* in_sizes, int n_in,
                              void* d_out, int out_size) {
    const int*   x        = (const int*)  d_in[0];
    const int*   t        = (const int*)  d_in[1];
    const int*   s2       = (const int*)  d_in[3];
    const float* h0       = (const float*)d_in[7];
    const int*   au       = (const int*)  d_in[8];
    const int*   ecols    = (const int*)  d_in[10];
    const float* evals    = (const float*)d_in[11];
    const float* loc_emb  = (const float*)d_in[12];
    const float* user_emb = (const float*)d_in[13];
    const float* pref     = (const float*)d_in[14];
    const float* W_proj   = (const float*)d_in[15];
    const float* b_proj   = (const float*)d_in[16];
    const float* W_gconv  = (const float*)d_in[17];
    const float* b_gconv  = (const float*)d_in[18];
    const float* W_ih     = (const float*)d_in[19];
    const float* W_hh     = (const float*)d_in[20];
    const float* b_ih     = (const float*)d_in[21];
    const float* b_hh     = (const float*)d_in[22];
    const float* W_fc     = (const float*)d_in[23];
    const float* b_fc     = (const float*)d_in[24];
    float* out = (float*)d_out;

    cudaFuncSetAttribute(k_fc_mma, cudaFuncAttributeMaxDynamicSharedMemorySize, FC_SMEM);

    k_init<<<GB_GATHER + HD + 1, 384>>>(ecols, evals, loc_emb, W_gconv, W_ih,
                                        W_proj, b_gconv, b_ih, b_hh, b_proj);
    k_packB<<<dim3(NLOC/32, HD/32), dim3(32, 32)>>>(W_fc);
    k_pproj<<<UBN, HH2>>>(au, user_emb, W_proj, b_proj);
    k_prebias<<<NLOC/64, 256>>>(W_fc, b_fc);
    k_transp<<<dim3(UBN/32, SQ/32), dim3(32, 32)>>>(t, s2);
    k_tabfused<<<NLOC/32, 384>>>();
    k_rnn2<<<UBN/2, HD>>>(x, W_hh, h0, out);
    k_sim2<<<UBN, 256>>>(x, pref);
    k_wsum<<<dim3(UBN, SQ/8), HD>>>();
    k_fc_mma<<<dim3((NLOC + 127)/128, SQ*UBN/256), 512, FC_SMEM>>>(out);
}

// round 15
// speedup vs baseline: 1.0986x; 1.0314x over previous
#include <cuda_runtime.h>
#include <cuda_bf16.h>
#include <cuda_fp16.h>
#include <math.h>
#include <stdint.h>

#define SQ   128
#define UBN  256
#define HD   128
#define HH2  256
#define NLOC 8000
#define DEG  16

// ---------------- scratch (device globals; no allocation allowed) ----------
__device__ float g_encpre[NLOC*HD];
__device__ float g_encwIH[NLOC*HD];
__device__ float g_encwP [NLOC*HH2];
__device__ float g_Wcomb [HD*384];
__device__ float g_rbias [HD];
__device__ float g_pbias [HH2];
__device__ float g_rnn   [SQ*UBN*HD];
__device__ float g_pproj [UBN*HH2];
__device__ float g_pu    [UBN*HD];
__device__ float g_sim   [UBN*SQ];
__device__ float g_tT [UBN*SQ];
__device__ float g_sxT[UBN*SQ];
__device__ float g_syT[UBN*SQ];
__device__ float g_prebias[(size_t)UBN*NLOC];
__device__ __half g_Ah[(size_t)SQ*UBN*HD];   // fp16 A, u-major rows (u*SQ+i)
__device__ __half g_Bh[(size_t)NLOC*HD];     // fp16 B

extern __shared__ float sm[];

// ---------------- helpers ----------------------------------------------------
__device__ __forceinline__ uint32_t s2u(const void* p) {
    uint32_t a;
    asm("{ .reg .u64 t; cvta.to.shared.u64 t, %1; cvt.u32.u64 %0, t; }"
        : "=r"(a) : "l"(p));
    return a;
}
__device__ __forceinline__ void ldsm4(uint32_t& r0, uint32_t& r1,
                                      uint32_t& r2, uint32_t& r3, uint32_t addr) {
    asm volatile("ldmatrix.sync.aligned.m8n8.x4.shared.b16 {%0,%1,%2,%3}, [%4];"
                 : "=r"(r0), "=r"(r1), "=r"(r2), "=r"(r3) : "r"(addr));
}
__device__ __forceinline__ void mma_f16(float* d, const uint32_t* a,
                                        const uint32_t* b) {
    asm volatile(
        "mma.sync.aligned.m16n8k16.row.col.f32.f16.f16.f32 "
        "{%0,%1,%2,%3}, {%4,%5,%6,%7}, {%8,%9}, {%0,%1,%2,%3};"
        : "+f"(d[0]), "+f"(d[1]), "+f"(d[2]), "+f"(d[3])
        : "r"(a[0]), "r"(a[1]), "r"(a[2]), "r"(a[3]), "r"(b[0]), "r"(b[1]));
}
__device__ __forceinline__ void cpa16(uint32_t dst, const void* src) {
    asm volatile("cp.async.cg.shared.global [%0], [%1], 16;"
                 :: "r"(dst), "l"(src) : "memory");
}
__device__ __forceinline__ void cpa_wait() {
    asm volatile("cp.async.commit_group;" ::: "memory");
    asm volatile("cp.async.wait_group 0;" ::: "memory");
}
// smem byte offset for row-major [row][128 x 16-bit] with XOR-16B swizzle
__device__ __forceinline__ uint32_t swz(uint32_t row, uint32_t byte) {
    return row*256 + ((((byte >> 4) ^ (row & 7)) << 4) | (byte & 15));
}
__device__ __forceinline__ float ftanh(float x) {
    float e = __expf(2.f * x);
    return 1.f - 2.f / (e + 1.f);
}

// ---------------- K1 (fused): gather | combw | bias --------------------------
#define GB_GATHER 2667
__global__ void __launch_bounds__(384) k_init(const int* __restrict__ cols,
                                              const float* __restrict__ vals,
                                              const float* __restrict__ loc_emb,
                                              const float* __restrict__ Wg,
                                              const float* __restrict__ Wih,
                                              const float* __restrict__ Wp,
                                              const float* __restrict__ bg,
                                              const float* __restrict__ b_ih,
                                              const float* __restrict__ b_hh,
                                              const float* __restrict__ bp) {
    int b = blockIdx.x, c = threadIdx.x;
    if (b < GB_GATHER) {
        int i = b*3 + (c >> 7);
        if (i < NLOC) {
            int h = c & 127;
            float acc = vals[NLOC*DEG + i] * loc_emb[i*HD + h];
            #pragma unroll
            for (int d = 0; d < DEG; d++) {
                int e = i*DEG + d;
                acc += vals[e] * loc_emb[cols[e]*HD + h];
            }
            g_encpre[i*HD + h] = acc;
        }
    } else if (b < GB_GATHER + HD) {
        __shared__ float wg[HD];
        int k = b - GB_GATHER;
        if (c < HD) wg[c] = Wg[k*HD + c];
        __syncthreads();
        float acc = 0.f;
        if (c < HD) {
            for (int j = 0; j < HD; j++) acc += wg[j] * Wih[j*HD + c];
        } else {
            int c2 = c - HD;
            for (int j = 0; j < HD; j++) acc += wg[j] * Wp[j*HH2 + c2];
        }
        g_Wcomb[k*384 + c] = acc;
    } else {
        __shared__ float sbg[HD];
        if (c < HD) sbg[c] = bg[c];
        __syncthreads();
        if (c < HD) {
            float acc = b_ih[c] + b_hh[c];
            for (int j = 0; j < HD; j++) acc += sbg[j] * Wih[j*HD + c];
            g_rbias[c] = acc;
        } else {
            int c2 = c - HD;
            float acc = bp[c2];
            for (int j = 0; j < HD; j++) acc += sbg[j] * Wp[j*HH2 + c2];
            g_pbias[c2] = acc;
        }
    }
}

// ---------------- K2c: fused table GEMM  encpre @ Wcomb ---------------------
__global__ void __launch_bounds__(384) k_tabfused() {
    __shared__ __align__(16) float at[128*36];   // at[k*36 + r]
    int r0 = blockIdx.x * 32, c = threadIdx.x;
    for (int q = c; q < 32*HD; q += 384) {
        int r = q >> 7, k = q & 127;
        at[k*36 + r] = g_encpre[(r0 + r)*HD + k];
    }
    float pbv = (c >= HD) ? g_pbias[c - HD] : 0.f;
    __syncthreads();
    float acc[32];
    #pragma unroll
    for (int r = 0; r < 32; r++) acc[r] = 0.f;
    #pragma unroll 4
    for (int k = 0; k < HD; k++) {
        float w = g_Wcomb[k*384 + c];
        #pragma unroll
        for (int rq = 0; rq < 8; rq++) {
            float4 av = *(const float4*)&at[k*36 + rq*4];
            acc[rq*4+0] += av.x * w;
            acc[rq*4+1] += av.y * w;
            acc[rq*4+2] += av.z * w;
            acc[rq*4+3] += av.w * w;
        }
    }
    if (c < HD) {
        for (int r = 0; r < 32; r++) g_encwIH[(r0 + r)*HD + c] = acc[r];
    } else {
        int c2 = c - HD;
        for (int r = 0; r < 32; r++)
            g_encwP[(size_t)(r0 + r)*HH2 + c2] = ftanh(acc[r] + pbv);
    }
}

// ---------------- K4: p_u + p_proj ------------------------------------------
__global__ void k_pproj(const int* __restrict__ au,
                        const float* __restrict__ user_emb,
                        const float* __restrict__ W_proj,
                        const float* __restrict__ b_proj) {
    __shared__ float pu[HD];
    int u = blockIdx.x, c = threadIdx.x;   // 256 threads
    if (c < HD) pu[c] = user_emb[au[u]*HD + c];
    __syncthreads();
    if (c < HD) g_pu[u*HD + c] = pu[c];
    float acc = b_proj[c];
    for (int k = 0; k < HD; k++) acc += pu[k] * W_proj[k*HH2 + c];
    g_pproj[u*HH2 + c] = ftanh(acc);
}

// ---------------- K5: RNN (+h_last directly to out tail) --------------------
__global__ void __launch_bounds__(128) k_rnn2(const int* __restrict__ x,
                                              const float* __restrict__ W_hh,
                                              const float* __restrict__ h0,
                                              float* __restrict__ out) {
    __shared__ __align__(16) float hs0[HD];
    __shared__ __align__(16) float hs1[HD];
    __shared__ int sidx[2];
    int j = threadIdx.x;
    int u0 = blockIdx.x * 2;

    float wr[HD];
    #pragma unroll
    for (int k = 0; k < HD; k++) wr[k] = W_hh[k*HD + j];
    float bias = g_rbias[j];
    hs0[j] = h0[u0*HD + j];
    hs1[j] = h0[(u0 + 1)*HD + j];
    __syncthreads();

    for (int t = 0; t < SQ; t++) {
        if (j < 2) sidx[j] = x[t*UBN + u0 + j];
        __syncthreads();
        float a0 = g_encwIH[sidx[0]*HD + j] + bias;
        float a1 = g_encwIH[sidx[1]*HD + j] + bias;
        const float4* h40 = (const float4*)hs0;
        const float4* h41 = (const float4*)hs1;
        #pragma unroll
        for (int k4 = 0; k4 < HD/4; k4++) {
            float4 v0 = h40[k4], v1 = h41[k4];
            a0 += wr[4*k4+0]*v0.x + wr[4*k4+1]*v0.y
                + wr[4*k4+2]*v0.z + wr[4*k4+3]*v0.w;
            a1 += wr[4*k4+0]*v1.x + wr[4*k4+1]*v1.y
                + wr[4*k4+2]*v1.z + wr[4*k4+3]*v1.w;
        }
        float n0 = ftanh(a0);
        float n1 = ftanh(a1);
        __syncthreads();
        hs0[j] = n0;
        hs1[j] = n1;
        g_rnn[(t*UBN + u0)*HD + j]     = n0;
        g_rnn[(t*UBN + u0 + 1)*HD + j] = n1;
    }
    // h_last -> out tail (layout [1][UBN][HD])
    size_t base = (size_t)SQ*UBN*NLOC;
    out[base + (size_t)u0*HD + j]       = hs0[j];
    out[base + (size_t)(u0 + 1)*HD + j] = hs1[j];
}

// ---------------- K6: sim[u][s] via encwP gather -----------------------------
__global__ void __launch_bounds__(256) k_sim2(const int* __restrict__ x,
                                              const float* __restrict__ pref) {
    __shared__ __align__(16) float pc[HH2];
    int u = blockIdx.x, tid = threadIdx.x;
    pc[tid] = g_pproj[u*HH2 + tid] + pref[tid];
    __syncthreads();
    int w = tid >> 5, lane = tid & 31;
    for (int s = w; s < SQ; s += 8) {
        int loc = x[s*UBN + u];
        const float4* row = (const float4*)&g_encwP[(size_t)loc*HH2];
        float acc = 0.f;
        #pragma unroll
        for (int q = 0; q < 2; q++) {
            float4 v = row[lane*2 + q];
            float4 p = *(const float4*)&pc[lane*8 + q*4];
            float d0 = p.x - v.x, d1 = p.y - v.y, d2 = p.z - v.z, d3 = p.w - v.w;
            acc += d0*d0 + d1*d1 + d2*d2 + d3*d3;
        }
        #pragma unroll
        for (int o = 16; o > 0; o >>= 1) acc += __shfl_down_sync(0xffffffffu, acc, o);
        if (lane == 0) {
            float z = sqrtf(acc + 1e-12f);
            g_sim[u*SQ + s] = 1.f / (1.f + __expf(z));
        }
    }
}

// ---------------- K6b: transpose t/s into [U][S] float layout ----------------
__global__ void k_transp(const int* __restrict__ t, const int* __restrict__ s2) {
    __shared__ float T[3][32][33];
    int u0 = blockIdx.x * 32, s0 = blockIdx.y * 32;
    int tx = threadIdx.x, ty = threadIdx.y;
    int s = s0 + ty, u = u0 + tx;
    T[0][ty][tx] = (float)t[s*UBN + u];
    T[1][ty][tx] = (float)s2[(s*UBN + u)*2 + 0];
    T[2][ty][tx] = (float)s2[(s*UBN + u)*2 + 1];
    __syncthreads();
    int uo = u0 + ty, so = s0 + tx;
    g_tT [uo*SQ + so] = T[0][tx][ty];
    g_sxT[uo*SQ + so] = T[1][tx][ty];
    g_syT[uo*SQ + so] = T[2][tx][ty];
}

// ---------------- K8: fused weights + weighted sum -> fp16 A ----------------
__global__ void __launch_bounds__(128) k_wsum() {
    __shared__ __align__(16) float wsm[8*SQ];   // w[q][j]
    __shared__ float ssum[8];
    const float K1 = 7.2722052166430399e-05f;   // 2*pi/86400
    const float K2 = 1.1574074074074074e-06f;   // 0.1/86400
    int u = blockIdx.x, ig = blockIdx.y, h = threadIdx.x;
    int ibase = ig * 8;

    const float* tT  = &g_tT [u*SQ];
    const float* sxT = &g_sxT[u*SQ];
    const float* syT = &g_syT[u*SQ];
    const float* sim = &g_sim[u*SQ];

    #pragma unroll
    for (int q8 = 0; q8 < 8; q8++) {
        int idx = q8*128 + h;
        int q = idx >> 7, j = idx & 127;
        int i = ibase + q;
        float w = 0.f;
        if (j <= i) {
            float dt = tT[i] - tT[j];
            float dx = sxT[i] - sxT[j];
            float dy = syT[i] - syT[j];
            float ds = sqrtf(dx*dx + dy*dy);
            float a  = (__cosf(dt * K1) + 1.f) * 0.5f * __expf(-dt * K2);
            float b  = __expf(-ds * 0.1f);
            w = (a*b + 1e-10f) * sim[j];
        }
        wsm[idx] = w;
    }
    __syncthreads();
    {
        int wp = h >> 5, lane = h & 31;
        #pragma unroll
        for (int rr = 0; rr < 2; rr++) {
            int q = wp + rr*4;
            float v = wsm[q*SQ + lane] + wsm[q*SQ + lane + 32]
                    + wsm[q*SQ + lane + 64] + wsm[q*SQ + lane + 96];
            #pragma unroll
            for (int o = 16; o > 0; o >>= 1) v += __shfl_down_sync(0xffffffffu, v, o);
            if (lane == 0) ssum[q] = v;
        }
    }
    __syncthreads();

    float acc[8];
    #pragma unroll
    for (int q = 0; q < 8; q++) acc[q] = 0.f;
    int jmax = ibase + 8;
    for (int j = 0; j < jmax; j++) {
        float r = g_rnn[(j*UBN + u)*HD + h];
        #pragma unroll
        for (int q = 0; q < 8; q++) acc[q] += wsm[q*SQ + j] * r;
    }
    #pragma unroll
    for (int q = 0; q < 8; q++) {
        int m = u*SQ + ibase + q;                 // u-major row
        g_Ah[(size_t)m*HD + h] = __float2half_rn(acc[q] / ssum[q]);
    }
}

// ---------------- K9a: pack/transpose Wfc top half -> fp16 ------------------
__global__ void k_packB(const float* __restrict__ Wfc) {
    __shared__ float t[32][33];
    int nx = blockIdx.x*32, ky = blockIdx.y*32;
    int tx = threadIdx.x, ty = threadIdx.y;
    t[ty][tx] = Wfc[(size_t)(ky + ty)*NLOC + nx + tx];
    __syncthreads();
    int n = nx + ty, k = ky + tx;
    g_Bh[(size_t)n*HD + k] = __float2half_rn(t[tx][ty]);
}

// ---------------- K9b: prebias, 16 users/thread, 4-way split ----------------
__global__ void __launch_bounds__(256) k_prebias(const float* __restrict__ Wfc,
                                                 const float* __restrict__ bfc) {
    __shared__ float spu[64*HD];   // 64 users x 128 k
    int tid = threadIdx.x;
    int n  = blockIdx.x*64 + (tid & 63);
    int ub = blockIdx.y*64;        // user base for this block
    int ug = tid >> 6;             // 0..3 -> users ub+ug*16 .. +15
    // stage 64 users' p_u
    for (int q = tid; q < 64*HD; q += 256)
        spu[q] = g_pu[(ub + (q >> 7))*HD + (q & 127)];
    __syncthreads();

    float acc[16];
    #pragma unroll
    for (int i = 0; i < 16; i++) acc[i] = 0.f;
    const float* pu = &spu[ug*16*HD];
    for (int k = 0; k < HD; k++) {
        float w = Wfc[(size_t)(HD + k)*NLOC + n];
        #pragma unroll
        for (int uu = 0; uu < 16; uu++)
            acc[uu] += pu[uu*HD + k] * w;
    }
    float b = bfc[n];
    #pragma unroll
    for (int uu = 0; uu < 16; uu++)
        g_prebias[(size_t)(ub + ug*16 + uu)*NLOC + n] = acc[uu] + b;
}

// ---------------- K10: single-group fp16 mma GEMM (round-11 proven) ---------
// Mtile=256 (u-major), Ntile=128. smem: A 64KB | B 32KB | prebias 1KB = 97KB
#define FCA_OFF  0
#define FCB_OFF  65536
#define FCPB_OFF 98304
#define FC_SMEM  99328

__global__ void __launch_bounds__(512, 1) k_fc_mma(float* __restrict__ out) {
    char* smc = (char*)sm;
    uint32_t smb = s2u(smc);
    int tid = threadIdx.x, wid = tid >> 5, lane = tid & 31;
    int n0 = blockIdx.x * 128;
    int m0 = blockIdx.y * 256;            // rows u-major: u = row>>7
    int u0 = m0 >> 7;
    int warpM = (wid >> 2) * 64;
    int warpN = (wid & 3) * 32;

    float acc[4][4][4];
    #pragma unroll
    for (int i = 0; i < 4; i++)
        #pragma unroll
        for (int j = 0; j < 4; j++)
            #pragma unroll
            for (int q = 0; q < 4; q++) acc[i][j][q] = 0.f;

    // ---- async load A (64KB) ----
    {
        const uint4* src = (const uint4*)g_Ah;
        #pragma unroll
        for (int it = 0; it < 8; it++) {
            int q = it*512 + tid;
            int rowg = q >> 4, c16 = q & 15;
            cpa16(smb + FCA_OFF + swz(rowg, c16*16),
                  &src[(size_t)(m0 + rowg)*16 + c16]);
        }
    }
    // ---- async load B (32KB), zero-fill OOB ----
    {
        const uint4* src = (const uint4*)g_Bh;
        #pragma unroll
        for (int it = 0; it < 4; it++) {
            int q = it*512 + tid;
            int rowg = q >> 4, c16 = q & 15;
            uint32_t d0 = smb + FCB_OFF + swz(rowg, c16*16);
            if (n0 + rowg < NLOC) {
                cpa16(d0, &src[(size_t)(n0 + rowg)*16 + c16]);
            } else {
                uint4 z = make_uint4(0u, 0u, 0u, 0u);
                *(uint4*)(smc + (d0 - smb)) = z;
            }
        }
    }
    // ---- stage prebias for 2 users x 128 cols ----
    {
        float* pb = (float*)(smc + FCPB_OFF);
        if (tid < 256) {
            int col = n0 + (tid & 127);
            float v = 0.f;
            if (col < NLOC) v = g_prebias[(size_t)(u0 + (tid >> 7))*NLOC + col];
            pb[tid] = v;
        }
    }
    cpa_wait();
    __syncthreads();

    uint32_t aRow = warpM + (lane & 15);
    uint32_t aByt = (lane >> 4) * 16;
    uint32_t bRow = warpN + ((lane >> 4) << 3) + (lane & 7);
    uint32_t bByt = ((lane >> 3) & 1) << 4;

    uint32_t aPl = smb + FCA_OFF;
    uint32_t bPl = smb + FCB_OFF;

    #pragma unroll
    for (int kk = 0; kk < 8; kk++) {
        uint32_t bb[8];
        ldsm4(bb[0], bb[1], bb[2], bb[3], bPl + swz(bRow,      kk*32 + bByt));
        ldsm4(bb[4], bb[5], bb[6], bb[7], bPl + swz(bRow + 16, kk*32 + bByt));
        #pragma unroll
        for (int mt = 0; mt < 4; mt++) {
            uint32_t a[4];
            ldsm4(a[0], a[1], a[2], a[3], aPl + swz(aRow + mt*16, kk*32 + aByt));
            #pragma unroll
            for (int nt = 0; nt < 4; nt++) mma_f16(acc[mt][nt], a, &bb[nt*2]);
        }
    }

    // ---- epilogue: decode (u, i), add staged prebias, write out ----
    const float* pb = (const float*)(smc + FCPB_OFF);
    #pragma unroll
    for (int mt = 0; mt < 4; mt++) {
        int moff = warpM + mt*16 + (lane >> 2);
        int ul = moff >> 7;
        int i  = moff & 127;
        size_t row0 = (size_t)(i*UBN + u0 + ul)*NLOC;
        size_t row1 = (size_t)((i + 8)*UBN + u0 + ul)*NLOC;
        #pragma unroll
        for (int nt = 0; nt < 4; nt++) {
            int cloc = warpN + nt*8 + (lane & 3)*2;
            int col  = n0 + cloc;
            if (col < NLOC) {
                float2 pbv = *(const float2*)&pb[(ul << 7) + cloc];
                float2 v0 = make_float2(acc[mt][nt][0] + pbv.x, acc[mt][nt][1] + pbv.y);
                float2 v1 = make_float2(acc[mt][nt][2] + pbv.x, acc[mt][nt][3] + pbv.y);
                *(float2*)&out[row0 + col] = v0;
                *(float2*)&out[row1 + col] = v1;
            }
        }
    }
}

// ---------------- launch ------------------------------------------------------
extern "C" void kernel_launch(void* const* d_in, const int* in_sizes, int n_in,
                              void* d_out, int out_size) {
    const int*   x        = (const int*)  d_in[0];
    const int*   t        = (const int*)  d_in[1];
    const int*   s2       = (const int*)  d_in[3];
    const float* h0       = (const float*)d_in[7];
    const int*   au       = (const int*)  d_in[8];
    const int*   ecols    = (const int*)  d_in[10];
    const float* evals    = (const float*)d_in[11];
    const float* loc_emb  = (const float*)d_in[12];
    const float* user_emb = (const float*)d_in[13];
    const float* pref     = (const float*)d_in[14];
    const float* W_proj   = (const float*)d_in[15];
    const float* b_proj   = (const float*)d_in[16];
    const float* W_gconv  = (const float*)d_in[17];
    const float* b_gconv  = (const float*)d_in[18];
    const float* W_ih     = (const float*)d_in[19];
    const float* W_hh     = (const float*)d_in[20];
    const float* b_ih     = (const float*)d_in[21];
    const float* b_hh     = (const float*)d_in[22];
    const float* W_fc     = (const float*)d_in[23];
    const float* b_fc     = (const float*)d_in[24];
    float* out = (float*)d_out;

    cudaFuncSetAttribute(k_fc_mma, cudaFuncAttributeMaxDynamicSharedMemorySize, FC_SMEM);

    k_init<<<GB_GATHER + HD + 1, 384>>>(ecols, evals, loc_emb, W_gconv, W_ih,
                                        W_proj, b_gconv, b_ih, b_hh, b_proj);
    k_packB<<<dim3(NLOC/32, HD/32), dim3(32, 32)>>>(W_fc);
    k_pproj<<<UBN, HH2>>>(au, user_emb, W_proj, b_proj);
    k_prebias<<<dim3(NLOC/64, UBN/64), 256>>>(W_fc, b_fc);
    k_transp<<<dim3(UBN/32, SQ/32), dim3(32, 32)>>>(t, s2);
    k_tabfused<<<NLOC/32, 384>>>();
    k_rnn2<<<UBN/2, HD>>>(x, W_hh, h0, out);
    k_sim2<<<UBN, 256>>>(x, pref);
    k_wsum<<<dim3(UBN, SQ/8), HD>>>();
    k_fc_mma<<<dim3((NLOC + 127)/128, SQ*UBN/256), 512, FC_SMEM>>>(out);
}

// round 16
// speedup vs baseline: 1.1031x; 1.0041x over previous
#include <cuda_runtime.h>
#include <cuda_bf16.h>
#include <cuda_fp16.h>
#include <math.h>
#include <stdint.h>

#define SQ   128
#define UBN  256
#define HD   128
#define HH2  256
#define NLOC 8000
#define DEG  16

// ---------------- scratch (device globals; no allocation allowed) ----------
__device__ float g_encpre[NLOC*HD];
__device__ float g_encwIH[NLOC*HD];
__device__ float g_encwP [NLOC*HH2];
__device__ float g_Wcomb [HD*384];
__device__ float g_rbias [HD];
__device__ float g_pbias [HH2];
__device__ float g_rnn   [SQ*UBN*HD];
__device__ float g_pproj [UBN*HH2];
__device__ float g_pu    [UBN*HD];
__device__ float g_sim   [UBN*SQ];
__device__ float g_tT [UBN*SQ];
__device__ float g_sxT[UBN*SQ];
__device__ float g_syT[UBN*SQ];
__device__ float g_prebias[(size_t)UBN*NLOC];
__device__ __half g_Ah[(size_t)SQ*UBN*HD];   // fp16 A, u-major rows (u*SQ+i)
__device__ __half g_Bh[(size_t)NLOC*HD];     // fp16 B

extern __shared__ float sm[];

// ---------------- helpers ----------------------------------------------------
__device__ __forceinline__ uint32_t s2u(const void* p) {
    uint32_t a;
    asm("{ .reg .u64 t; cvta.to.shared.u64 t, %1; cvt.u32.u64 %0, t; }"
        : "=r"(a) : "l"(p));
    return a;
}
__device__ __forceinline__ void ldsm4(uint32_t& r0, uint32_t& r1,
                                      uint32_t& r2, uint32_t& r3, uint32_t addr) {
    asm volatile("ldmatrix.sync.aligned.m8n8.x4.shared.b16 {%0,%1,%2,%3}, [%4];"
                 : "=r"(r0), "=r"(r1), "=r"(r2), "=r"(r3) : "r"(addr));
}
__device__ __forceinline__ void mma_f16(float* d, const uint32_t* a,
                                        const uint32_t* b) {
    asm volatile(
        "mma.sync.aligned.m16n8k16.row.col.f32.f16.f16.f32 "
        "{%0,%1,%2,%3}, {%4,%5,%6,%7}, {%8,%9}, {%0,%1,%2,%3};"
        : "+f"(d[0]), "+f"(d[1]), "+f"(d[2]), "+f"(d[3])
        : "r"(a[0]), "r"(a[1]), "r"(a[2]), "r"(a[3]), "r"(b[0]), "r"(b[1]));
}
__device__ __forceinline__ void cpa16(uint32_t dst, const void* src) {
    asm volatile("cp.async.cg.shared.global [%0], [%1], 16;"
                 :: "r"(dst), "l"(src) : "memory");
}
__device__ __forceinline__ void cpa_wait() {
    asm volatile("cp.async.commit_group;" ::: "memory");
    asm volatile("cp.async.wait_group 0;" ::: "memory");
}
// smem byte offset for row-major [row][128 x 16-bit] with XOR-16B swizzle
__device__ __forceinline__ uint32_t swz(uint32_t row, uint32_t byte) {
    return row*256 + ((((byte >> 4) ^ (row & 7)) << 4) | (byte & 15));
}
__device__ __forceinline__ float ftanh(float x) {
    float e = __expf(2.f * x);
    return 1.f - 2.f / (e + 1.f);
}

// ---------------- K1 (fused): gather | combw | bias --------------------------
#define GB_GATHER 2667
__global__ void __launch_bounds__(384) k_init(const int* __restrict__ cols,
                                              const float* __restrict__ vals,
                                              const float* __restrict__ loc_emb,
                                              const float* __restrict__ Wg,
                                              const float* __restrict__ Wih,
                                              const float* __restrict__ Wp,
                                              const float* __restrict__ bg,
                                              const float* __restrict__ b_ih,
                                              const float* __restrict__ b_hh,
                                              const float* __restrict__ bp) {
    int b = blockIdx.x, c = threadIdx.x;
    if (b < GB_GATHER) {
        int i = b*3 + (c >> 7);
        if (i < NLOC) {
            int h = c & 127;
            float acc = vals[NLOC*DEG + i] * loc_emb[i*HD + h];
            #pragma unroll
            for (int d = 0; d < DEG; d++) {
                int e = i*DEG + d;
                acc += vals[e] * loc_emb[cols[e]*HD + h];
            }
            g_encpre[i*HD + h] = acc;
        }
    } else if (b < GB_GATHER + HD) {
        __shared__ float wg[HD];
        int k = b - GB_GATHER;
        if (c < HD) wg[c] = Wg[k*HD + c];
        __syncthreads();
        float acc = 0.f;
        if (c < HD) {
            for (int j = 0; j < HD; j++) acc += wg[j] * Wih[j*HD + c];
        } else {
            int c2 = c - HD;
            for (int j = 0; j < HD; j++) acc += wg[j] * Wp[j*HH2 + c2];
        }
        g_Wcomb[k*384 + c] = acc;
    } else {
        __shared__ float sbg[HD];
        if (c < HD) sbg[c] = bg[c];
        __syncthreads();
        if (c < HD) {
            float acc = b_ih[c] + b_hh[c];
            for (int j = 0; j < HD; j++) acc += sbg[j] * Wih[j*HD + c];
            g_rbias[c] = acc;
        } else {
            int c2 = c - HD;
            float acc = bp[c2];
            for (int j = 0; j < HD; j++) acc += sbg[j] * Wp[j*HH2 + c2];
            g_pbias[c2] = acc;
        }
    }
}

// ---------------- K2c: fused table GEMM  encpre @ Wcomb ---------------------
__global__ void __launch_bounds__(384) k_tabfused() {
    __shared__ __align__(16) float at[128*36];   // at[k*36 + r]
    int r0 = blockIdx.x * 32, c = threadIdx.x;
    for (int q = c; q < 32*HD; q += 384) {
        int r = q >> 7, k = q & 127;
        at[k*36 + r] = g_encpre[(r0 + r)*HD + k];
    }
    float pbv = (c >= HD) ? g_pbias[c - HD] : 0.f;
    __syncthreads();
    float acc[32];
    #pragma unroll
    for (int r = 0; r < 32; r++) acc[r] = 0.f;
    #pragma unroll 4
    for (int k = 0; k < HD; k++) {
        float w = g_Wcomb[k*384 + c];
        #pragma unroll
        for (int rq = 0; rq < 8; rq++) {
            float4 av = *(const float4*)&at[k*36 + rq*4];
            acc[rq*4+0] += av.x * w;
            acc[rq*4+1] += av.y * w;
            acc[rq*4+2] += av.z * w;
            acc[rq*4+3] += av.w * w;
        }
    }
    if (c < HD) {
        for (int r = 0; r < 32; r++) g_encwIH[(r0 + r)*HD + c] = acc[r];
    } else {
        int c2 = c - HD;
        for (int r = 0; r < 32; r++)
            g_encwP[(size_t)(r0 + r)*HH2 + c2] = ftanh(acc[r] + pbv);
    }
}

// ---------------- K4: p_u + p_proj ------------------------------------------
__global__ void k_pproj(const int* __restrict__ au,
                        const float* __restrict__ user_emb,
                        const float* __restrict__ W_proj,
                        const float* __restrict__ b_proj) {
    __shared__ float pu[HD];
    int u = blockIdx.x, c = threadIdx.x;   // 256 threads
    if (c < HD) pu[c] = user_emb[au[u]*HD + c];
    __syncthreads();
    if (c < HD) g_pu[u*HD + c] = pu[c];
    float acc = b_proj[c];
    for (int k = 0; k < HD; k++) acc += pu[k] * W_proj[k*HH2 + c];
    g_pproj[u*HH2 + c] = ftanh(acc);
}

// ---------------- K5: RNN (+h_last directly to out tail) --------------------
__global__ void __launch_bounds__(128) k_rnn2(const int* __restrict__ x,
                                              const float* __restrict__ W_hh,
                                              const float* __restrict__ h0,
                                              float* __restrict__ out) {
    __shared__ __align__(16) float hs0[HD];
    __shared__ __align__(16) float hs1[HD];
    __shared__ int sidx[2];
    int j = threadIdx.x;
    int u0 = blockIdx.x * 2;

    float wr[HD];
    #pragma unroll
    for (int k = 0; k < HD; k++) wr[k] = W_hh[k*HD + j];
    float bias = g_rbias[j];
    hs0[j] = h0[u0*HD + j];
    hs1[j] = h0[(u0 + 1)*HD + j];
    __syncthreads();

    for (int t = 0; t < SQ; t++) {
        if (j < 2) sidx[j] = x[t*UBN + u0 + j];
        __syncthreads();
        float a0 = g_encwIH[sidx[0]*HD + j] + bias;
        float a1 = g_encwIH[sidx[1]*HD + j] + bias;
        const float4* h40 = (const float4*)hs0;
        const float4* h41 = (const float4*)hs1;
        #pragma unroll
        for (int k4 = 0; k4 < HD/4; k4++) {
            float4 v0 = h40[k4], v1 = h41[k4];
            a0 += wr[4*k4+0]*v0.x + wr[4*k4+1]*v0.y
                + wr[4*k4+2]*v0.z + wr[4*k4+3]*v0.w;
            a1 += wr[4*k4+0]*v1.x + wr[4*k4+1]*v1.y
                + wr[4*k4+2]*v1.z + wr[4*k4+3]*v1.w;
        }
        float n0 = ftanh(a0);
        float n1 = ftanh(a1);
        __syncthreads();
        hs0[j] = n0;
        hs1[j] = n1;
        g_rnn[(t*UBN + u0)*HD + j]     = n0;
        g_rnn[(t*UBN + u0 + 1)*HD + j] = n1;
    }
    // h_last -> out tail (layout [1][UBN][HD])
    size_t base = (size_t)SQ*UBN*NLOC;
    out[base + (size_t)u0*HD + j]       = hs0[j];
    out[base + (size_t)(u0 + 1)*HD + j] = hs1[j];
}

// ---------------- K6: sim[u][s] via encwP gather -----------------------------
__global__ void __launch_bounds__(256) k_sim2(const int* __restrict__ x,
                                              const float* __restrict__ pref) {
    __shared__ __align__(16) float pc[HH2];
    int u = blockIdx.x, tid = threadIdx.x;
    pc[tid] = g_pproj[u*HH2 + tid] + pref[tid];
    __syncthreads();
    int w = tid >> 5, lane = tid & 31;
    for (int s = w; s < SQ; s += 8) {
        int loc = x[s*UBN + u];
        const float4* row = (const float4*)&g_encwP[(size_t)loc*HH2];
        float acc = 0.f;
        #pragma unroll
        for (int q = 0; q < 2; q++) {
            float4 v = row[lane*2 + q];
            float4 p = *(const float4*)&pc[lane*8 + q*4];
            float d0 = p.x - v.x, d1 = p.y - v.y, d2 = p.z - v.z, d3 = p.w - v.w;
            acc += d0*d0 + d1*d1 + d2*d2 + d3*d3;
        }
        #pragma unroll
        for (int o = 16; o > 0; o >>= 1) acc += __shfl_down_sync(0xffffffffu, acc, o);
        if (lane == 0) {
            float z = sqrtf(acc + 1e-12f);
            g_sim[u*SQ + s] = 1.f / (1.f + __expf(z));
        }
    }
}

// ---------------- K6b: transpose t/s into [U][S] float layout ----------------
__global__ void k_transp(const int* __restrict__ t, const int* __restrict__ s2) {
    __shared__ float T[3][32][33];
    int u0 = blockIdx.x * 32, s0 = blockIdx.y * 32;
    int tx = threadIdx.x, ty = threadIdx.y;
    int s = s0 + ty, u = u0 + tx;
    T[0][ty][tx] = (float)t[s*UBN + u];
    T[1][ty][tx] = (float)s2[(s*UBN + u)*2 + 0];
    T[2][ty][tx] = (float)s2[(s*UBN + u)*2 + 1];
    __syncthreads();
    int uo = u0 + ty, so = s0 + tx;
    g_tT [uo*SQ + so] = T[0][tx][ty];
    g_sxT[uo*SQ + so] = T[1][tx][ty];
    g_syT[uo*SQ + so] = T[2][tx][ty];
}

// ---------------- K8: fused weights + weighted sum -> fp16 A ----------------
__global__ void __launch_bounds__(128) k_wsum() {
    __shared__ __align__(16) float wsm[8*SQ];   // w[q][j]
    __shared__ float ssum[8];
    const float K1 = 7.2722052166430399e-05f;   // 2*pi/86400
    const float K2 = 1.1574074074074074e-06f;   // 0.1/86400
    int u = blockIdx.x, ig = blockIdx.y, h = threadIdx.x;
    int ibase = ig * 8;

    const float* tT  = &g_tT [u*SQ];
    const float* sxT = &g_sxT[u*SQ];
    const float* syT = &g_syT[u*SQ];
    const float* sim = &g_sim[u*SQ];

    #pragma unroll
    for (int q8 = 0; q8 < 8; q8++) {
        int idx = q8*128 + h;
        int q = idx >> 7, j = idx & 127;
        int i = ibase + q;
        float w = 0.f;
        if (j <= i) {
            float dt = tT[i] - tT[j];
            float dx = sxT[i] - sxT[j];
            float dy = syT[i] - syT[j];
            float ds = sqrtf(dx*dx + dy*dy);
            float a  = (__cosf(dt * K1) + 1.f) * 0.5f * __expf(-dt * K2);
            float b  = __expf(-ds * 0.1f);
            w = (a*b + 1e-10f) * sim[j];
        }
        wsm[idx] = w;
    }
    __syncthreads();
    {
        int wp = h >> 5, lane = h & 31;
        #pragma unroll
        for (int rr = 0; rr < 2; rr++) {
            int q = wp + rr*4;
            float v = wsm[q*SQ + lane] + wsm[q*SQ + lane + 32]
                    + wsm[q*SQ + lane + 64] + wsm[q*SQ + lane + 96];
            #pragma unroll
            for (int o = 16; o > 0; o >>= 1) v += __shfl_down_sync(0xffffffffu, v, o);
            if (lane == 0) ssum[q] = v;
        }
    }
    __syncthreads();

    float acc[8];
    #pragma unroll
    for (int q = 0; q < 8; q++) acc[q] = 0.f;
    int jmax = ibase + 8;
    for (int j = 0; j < jmax; j++) {
        float r = g_rnn[(j*UBN + u)*HD + h];
        #pragma unroll
        for (int q = 0; q < 8; q++) acc[q] += wsm[q*SQ + j] * r;
    }
    #pragma unroll
    for (int q = 0; q < 8; q++) {
        int m = u*SQ + ibase + q;                 // u-major row
        g_Ah[(size_t)m*HD + h] = __float2half_rn(acc[q] / ssum[q]);
    }
}

// ---------------- K9a: pack/transpose Wfc top half -> fp16 ------------------
__global__ void k_packB(const float* __restrict__ Wfc) {
    __shared__ float t[32][33];
    int nx = blockIdx.x*32, ky = blockIdx.y*32;
    int tx = threadIdx.x, ty = threadIdx.y;
    t[ty][tx] = Wfc[(size_t)(ky + ty)*NLOC + nx + tx];
    __syncthreads();
    int n = nx + ty, k = ky + tx;
    g_Bh[(size_t)n*HD + k] = __float2half_rn(t[tx][ty]);
}

// ---------------- K9b: prebias, 16 users/thread, 4-way split ----------------
__global__ void __launch_bounds__(256) k_prebias(const float* __restrict__ Wfc,
                                                 const float* __restrict__ bfc) {
    __shared__ float spu[64*HD];   // 64 users x 128 k
    int tid = threadIdx.x;
    int n  = blockIdx.x*64 + (tid & 63);
    int ub = blockIdx.y*64;        // user base for this block
    int ug = tid >> 6;             // 0..3 -> users ub+ug*16 .. +15
    for (int q = tid; q < 64*HD; q += 256)
        spu[q] = g_pu[(ub + (q >> 7))*HD + (q & 127)];
    __syncthreads();

    float acc[16];
    #pragma unroll
    for (int i = 0; i < 16; i++) acc[i] = 0.f;
    const float* pu = &spu[ug*16*HD];
    for (int k = 0; k < HD; k++) {
        float w = Wfc[(size_t)(HD + k)*NLOC + n];
        #pragma unroll
        for (int uu = 0; uu < 16; uu++)
            acc[uu] += pu[uu*HD + k] * w;
    }
    float b = bfc[n];
    #pragma unroll
    for (int uu = 0; uu < 16; uu++)
        g_prebias[(size_t)(ub + ug*16 + uu)*NLOC + n] = acc[uu] + b;
}

// ---------------- K10: fp16 mma GEMM, Mtile=128 (1 user), 2 CTAs/SM ---------
// smem: A 32KB | B 32KB | prebias 512B = 65KB
#define FCA_OFF  0
#define FCB_OFF  32768
#define FCPB_OFF 65536
#define FC_SMEM  66048

__global__ void __launch_bounds__(256, 2) k_fc_mma(float* __restrict__ out) {
    char* smc = (char*)sm;
    uint32_t smb = s2u(smc);
    int tid = threadIdx.x, wid = tid >> 5, lane = tid & 31;
    int n0 = blockIdx.x * 128;
    int m0 = blockIdx.y * 128;            // rows u-major: one user per CTA
    int u0 = m0 >> 7;
    int warpM = (wid >> 2) * 64;          // 0, 64
    int warpN = (wid & 3) * 32;           // 0,32,64,96

    float acc[4][4][4];
    #pragma unroll
    for (int i = 0; i < 4; i++)
        #pragma unroll
        for (int j = 0; j < 4; j++)
            #pragma unroll
            for (int q = 0; q < 4; q++) acc[i][j][q] = 0.f;

    // ---- async load A (32KB) ----
    {
        const uint4* src = (const uint4*)g_Ah;
        #pragma unroll
        for (int it = 0; it < 8; it++) {
            int q = it*256 + tid;                 // 0..2047
            int rowg = q >> 4, c16 = q & 15;
            cpa16(smb + FCA_OFF + swz(rowg, c16*16),
                  &src[(size_t)(m0 + rowg)*16 + c16]);
        }
    }
    // ---- async load B (32KB), zero-fill OOB ----
    {
        const uint4* src = (const uint4*)g_Bh;
        #pragma unroll
        for (int it = 0; it < 8; it++) {
            int q = it*256 + tid;                 // 0..2047
            int rowg = q >> 4, c16 = q & 15;
            uint32_t d0 = smb + FCB_OFF + swz(rowg, c16*16);
            if (n0 + rowg < NLOC) {
                cpa16(d0, &src[(size_t)(n0 + rowg)*16 + c16]);
            } else {
                uint4 z = make_uint4(0u, 0u, 0u, 0u);
                *(uint4*)(smc + (d0 - smb)) = z;
            }
        }
    }
    // ---- stage prebias for 1 user x 128 cols ----
    {
        float* pb = (float*)(smc + FCPB_OFF);
        if (tid < 128) {
            int col = n0 + tid;
            float v = 0.f;
            if (col < NLOC) v = g_prebias[(size_t)u0*NLOC + col];
            pb[tid] = v;
        }
    }
    cpa_wait();
    __syncthreads();

    uint32_t aRow = warpM + (lane & 15);
    uint32_t aByt = (lane >> 4) * 16;
    uint32_t bRow = warpN + ((lane >> 4) << 3) + (lane & 7);
    uint32_t bByt = ((lane >> 3) & 1) << 4;

    uint32_t aPl = smb + FCA_OFF;
    uint32_t bPl = smb + FCB_OFF;

    #pragma unroll
    for (int kk = 0; kk < 8; kk++) {
        uint32_t bb[8];
        ldsm4(bb[0], bb[1], bb[2], bb[3], bPl + swz(bRow,      kk*32 + bByt));
        ldsm4(bb[4], bb[5], bb[6], bb[7], bPl + swz(bRow + 16, kk*32 + bByt));
        #pragma unroll
        for (int mt = 0; mt < 4; mt++) {
            uint32_t a[4];
            ldsm4(a[0], a[1], a[2], a[3], aPl + swz(aRow + mt*16, kk*32 + aByt));
            #pragma unroll
            for (int nt = 0; nt < 4; nt++) mma_f16(acc[mt][nt], a, &bb[nt*2]);
        }
    }

    // ---- epilogue: row i of user u0, add staged prebias, write out ----
    const float* pb = (const float*)(smc + FCPB_OFF);
    #pragma unroll
    for (int mt = 0; mt < 4; mt++) {
        int i = warpM + mt*16 + (lane >> 2);      // 0..127
        size_t row0 = (size_t)(i*UBN + u0)*NLOC;
        size_t row1 = (size_t)((i + 8)*UBN + u0)*NLOC;
        #pragma unroll
        for (int nt = 0; nt < 4; nt++) {
            int cloc = warpN + nt*8 + (lane & 3)*2;
            int col  = n0 + cloc;
            if (col < NLOC) {
                float2 pbv = *(const float2*)&pb[cloc];
                float2 v0 = make_float2(acc[mt][nt][0] + pbv.x, acc[mt][nt][1] + pbv.y);
                float2 v1 = make_float2(acc[mt][nt][2] + pbv.x, acc[mt][nt][3] + pbv.y);
                *(float2*)&out[row0 + col] = v0;
                *(float2*)&out[row1 + col] = v1;
            }
        }
    }
}

// ---------------- launch ------------------------------------------------------
extern "C" void kernel_launch(void* const* d_in, const int* in_sizes, int n_in,
                              void* d_out, int out_size) {
    const int*   x        = (const int*)  d_in[0];
    const int*   t        = (const int*)  d_in[1];
    const int*   s2       = (const int*)  d_in[3];
    const float* h0       = (const float*)d_in[7];
    const int*   au       = (const int*)  d_in[8];
    const int*   ecols    = (const int*)  d_in[10];
    const float* evals    = (const float*)d_in[11];
    const float* loc_emb  = (const float*)d_in[12];
    const float* user_emb = (const float*)d_in[13];
    const float* pref     = (const float*)d_in[14];
    const float* W_proj   = (const float*)d_in[15];
    const float* b_proj   = (const float*)d_in[16];
    const float* W_gconv  = (const float*)d_in[17];
    const float* b_gconv  = (const float*)d_in[18];
    const float* W_ih     = (const float*)d_in[19];
    const float* W_hh     = (const float*)d_in[20];
    const float* b_ih     = (const float*)d_in[21];
    const float* b_hh     = (const float*)d_in[22];
    const float* W_fc     = (const float*)d_in[23];
    const float* b_fc     = (const float*)d_in[24];
    float* out = (float*)d_out;

    cudaFuncSetAttribute(k_fc_mma, cudaFuncAttributeMaxDynamicSharedMemorySize, FC_SMEM);

    k_init<<<GB_GATHER + HD + 1, 384>>>(ecols, evals, loc_emb, W_gconv, W_ih,
                                        W_proj, b_gconv, b_ih, b_hh, b_proj);
    k_packB<<<dim3(NLOC/32, HD/32), dim3(32, 32)>>>(W_fc);
    k_pproj<<<UBN, HH2>>>(au, user_emb, W_proj, b_proj);
    k_prebias<<<dim3(NLOC/64, UBN/64), 256>>>(W_fc, b_fc);
    k_transp<<<dim3(UBN/32, SQ/32), dim3(32, 32)>>>(t, s2);
    k_tabfused<<<NLOC/32, 384>>>();
    k_rnn2<<<UBN/2, HD>>>(x, W_hh, h0, out);
    k_sim2<<<UBN, 256>>>(x, pref);
    k_wsum<<<dim3(UBN, SQ/8), HD>>>();
    k_fc_mma<<<dim3((NLOC + 127)/128, SQ*UBN/128), 256, FC_SMEM>>>(out);
}

// round 17
// speedup vs baseline: 1.1279x; 1.0225x over previous
#include <cuda_runtime.h>
#include <cuda_bf16.h>
#include <cuda_fp16.h>
#include <math.h>
#include <stdint.h>

#define SQ   128
#define UBN  256
#define HD   128
#define HH2  256
#define NLOC 8000
#define DEG  16

// ---------------- scratch (device globals; no allocation allowed) ----------
__device__ float g_encpre[NLOC*HD];
__device__ float g_encwIH[NLOC*HD];
__device__ float g_encwP [NLOC*HH2];
__device__ float g_Wcomb [HD*384];
__device__ float g_rbias [HD];
__device__ float g_pbias [HH2];
__device__ float g_rnn   [SQ*UBN*HD];
__device__ float g_pproj [UBN*HH2];
__device__ float g_pu    [UBN*HD];
__device__ float g_sim   [UBN*SQ];
__device__ float g_tT [UBN*SQ];
__device__ float g_sxT[UBN*SQ];
__device__ float g_syT[UBN*SQ];
__device__ float g_prebias[(size_t)UBN*NLOC];
__device__ __half g_Ah[(size_t)SQ*UBN*HD];   // fp16 A, u-major rows (u*SQ+i)
__device__ __half g_Bh[(size_t)NLOC*HD];     // fp16 B

extern __shared__ float sm[];

// ---------------- helpers ----------------------------------------------------
__device__ __forceinline__ uint32_t s2u(const void* p) {
    uint32_t a;
    asm("{ .reg .u64 t; cvta.to.shared.u64 t, %1; cvt.u32.u64 %0, t; }"
        : "=r"(a) : "l"(p));
    return a;
}
__device__ __forceinline__ void ldsm4(uint32_t& r0, uint32_t& r1,
                                      uint32_t& r2, uint32_t& r3, uint32_t addr) {
    asm volatile("ldmatrix.sync.aligned.m8n8.x4.shared.b16 {%0,%1,%2,%3}, [%4];"
                 : "=r"(r0), "=r"(r1), "=r"(r2), "=r"(r3) : "r"(addr));
}
__device__ __forceinline__ void mma_f16(float* d, const uint32_t* a,
                                        const uint32_t* b) {
    asm volatile(
        "mma.sync.aligned.m16n8k16.row.col.f32.f16.f16.f32 "
        "{%0,%1,%2,%3}, {%4,%5,%6,%7}, {%8,%9}, {%0,%1,%2,%3};"
        : "+f"(d[0]), "+f"(d[1]), "+f"(d[2]), "+f"(d[3])
        : "r"(a[0]), "r"(a[1]), "r"(a[2]), "r"(a[3]), "r"(b[0]), "r"(b[1]));
}
__device__ __forceinline__ void cpa16(uint32_t dst, const void* src) {
    asm volatile("cp.async.cg.shared.global [%0], [%1], 16;"
                 :: "r"(dst), "l"(src) : "memory");
}
__device__ __forceinline__ void cpa_wait() {
    asm volatile("cp.async.commit_group;" ::: "memory");
    asm volatile("cp.async.wait_group 0;" ::: "memory");
}
__device__ __forceinline__ void stg_cs8(float* p, float2 v) {
    asm volatile("st.global.cs.v2.f32 [%0], {%1, %2};"
                 :: "l"(p), "f"(v.x), "f"(v.y) : "memory");
}
// smem byte offset for row-major [row][128 x 16-bit] with XOR-16B swizzle
__device__ __forceinline__ uint32_t swz(uint32_t row, uint32_t byte) {
    return row*256 + ((((byte >> 4) ^ (row & 7)) << 4) | (byte & 15));
}
__device__ __forceinline__ float ftanh(float x) {
    float e = __expf(2.f * x);
    return 1.f - 2.f / (e + 1.f);
}

// ---------------- K1 (fused): gather | combw | bias --------------------------
#define GB_GATHER 2667
__global__ void __launch_bounds__(384) k_init(const int* __restrict__ cols,
                                              const float* __restrict__ vals,
                                              const float* __restrict__ loc_emb,
                                              const float* __restrict__ Wg,
                                              const float* __restrict__ Wih,
                                              const float* __restrict__ Wp,
                                              const float* __restrict__ bg,
                                              const float* __restrict__ b_ih,
                                              const float* __restrict__ b_hh,
                                              const float* __restrict__ bp) {
    int b = blockIdx.x, c = threadIdx.x;
    if (b < GB_GATHER) {
        int i = b*3 + (c >> 7);
        if (i < NLOC) {
            int h = c & 127;
            float acc = vals[NLOC*DEG + i] * loc_emb[i*HD + h];
            #pragma unroll
            for (int d = 0; d < DEG; d++) {
                int e = i*DEG + d;
                acc += vals[e] * loc_emb[cols[e]*HD + h];
            }
            g_encpre[i*HD + h] = acc;
        }
    } else if (b < GB_GATHER + HD) {
        __shared__ float wg[HD];
        int k = b - GB_GATHER;
        if (c < HD) wg[c] = Wg[k*HD + c];
        __syncthreads();
        float acc = 0.f;
        if (c < HD) {
            for (int j = 0; j < HD; j++) acc += wg[j] * Wih[j*HD + c];
        } else {
            int c2 = c - HD;
            for (int j = 0; j < HD; j++) acc += wg[j] * Wp[j*HH2 + c2];
        }
        g_Wcomb[k*384 + c] = acc;
    } else {
        __shared__ float sbg[HD];
        if (c < HD) sbg[c] = bg[c];
        __syncthreads();
        if (c < HD) {
            float acc = b_ih[c] + b_hh[c];
            for (int j = 0; j < HD; j++) acc += sbg[j] * Wih[j*HD + c];
            g_rbias[c] = acc;
        } else {
            int c2 = c - HD;
            float acc = bp[c2];
            for (int j = 0; j < HD; j++) acc += sbg[j] * Wp[j*HH2 + c2];
            g_pbias[c2] = acc;
        }
    }
}

// ---------------- K2c: fused table GEMM, 16 rows/block (500 blocks) ---------
__global__ void __launch_bounds__(384) k_tabfused() {
    __shared__ __align__(16) float at[128*20];   // at[k*20 + r], 16 rows + pad
    int r0 = blockIdx.x * 16, c = threadIdx.x;
    for (int q = c; q < 16*HD; q += 384) {
        int r = q >> 7, k = q & 127;
        at[k*20 + r] = g_encpre[(r0 + r)*HD + k];
    }
    float pbv = (c >= HD) ? g_pbias[c - HD] : 0.f;
    __syncthreads();
    float acc[16];
    #pragma unroll
    for (int r = 0; r < 16; r++) acc[r] = 0.f;
    #pragma unroll 4
    for (int k = 0; k < HD; k++) {
        float w = g_Wcomb[k*384 + c];
        #pragma unroll
        for (int rq = 0; rq < 4; rq++) {
            float4 av = *(const float4*)&at[k*20 + rq*4];
            acc[rq*4+0] += av.x * w;
            acc[rq*4+1] += av.y * w;
            acc[rq*4+2] += av.z * w;
            acc[rq*4+3] += av.w * w;
        }
    }
    if (c < HD) {
        for (int r = 0; r < 16; r++) g_encwIH[(r0 + r)*HD + c] = acc[r];
    } else {
        int c2 = c - HD;
        for (int r = 0; r < 16; r++)
            g_encwP[(size_t)(r0 + r)*HH2 + c2] = ftanh(acc[r] + pbv);
    }
}

// ---------------- K4: p_u + p_proj ------------------------------------------
__global__ void k_pproj(const int* __restrict__ au,
                        const float* __restrict__ user_emb,
                        const float* __restrict__ W_proj,
                        const float* __restrict__ b_proj) {
    __shared__ float pu[HD];
    int u = blockIdx.x, c = threadIdx.x;   // 256 threads
    if (c < HD) pu[c] = user_emb[au[u]*HD + c];
    __syncthreads();
    if (c < HD) g_pu[u*HD + c] = pu[c];
    float acc = b_proj[c];
    for (int k = 0; k < HD; k++) acc += pu[k] * W_proj[k*HH2 + c];
    g_pproj[u*HH2 + c] = ftanh(acc);
}

// ---------------- K5: RNN (+h_last directly to out tail) --------------------
__global__ void __launch_bounds__(128) k_rnn2(const int* __restrict__ x,
                                              const float* __restrict__ W_hh,
                                              const float* __restrict__ h0,
                                              float* __restrict__ out) {
    __shared__ __align__(16) float hs0[HD];
    __shared__ __align__(16) float hs1[HD];
    __shared__ int sidx[2];
    int j = threadIdx.x;
    int u0 = blockIdx.x * 2;

    float wr[HD];
    #pragma unroll
    for (int k = 0; k < HD; k++) wr[k] = W_hh[k*HD + j];
    float bias = g_rbias[j];
    hs0[j] = h0[u0*HD + j];
    hs1[j] = h0[(u0 + 1)*HD + j];
    __syncthreads();

    for (int t = 0; t < SQ; t++) {
        if (j < 2) sidx[j] = x[t*UBN + u0 + j];
        __syncthreads();
        float a0 = g_encwIH[sidx[0]*HD + j] + bias;
        float a1 = g_encwIH[sidx[1]*HD + j] + bias;
        const float4* h40 = (const float4*)hs0;
        const float4* h41 = (const float4*)hs1;
        #pragma unroll
        for (int k4 = 0; k4 < HD/4; k4++) {
            float4 v0 = h40[k4], v1 = h41[k4];
            a0 += wr[4*k4+0]*v0.x + wr[4*k4+1]*v0.y
                + wr[4*k4+2]*v0.z + wr[4*k4+3]*v0.w;
            a1 += wr[4*k4+0]*v1.x + wr[4*k4+1]*v1.y
                + wr[4*k4+2]*v1.z + wr[4*k4+3]*v1.w;
        }
        float n0 = ftanh(a0);
        float n1 = ftanh(a1);
        __syncthreads();
        hs0[j] = n0;
        hs1[j] = n1;
        g_rnn[(t*UBN + u0)*HD + j]     = n0;
        g_rnn[(t*UBN + u0 + 1)*HD + j] = n1;
    }
    size_t base = (size_t)SQ*UBN*NLOC;
    out[base + (size_t)u0*HD + j]       = hs0[j];
    out[base + (size_t)(u0 + 1)*HD + j] = hs1[j];
}

// ---------------- K6: sim[u][s] via encwP gather -----------------------------
__global__ void __launch_bounds__(256) k_sim2(const int* __restrict__ x,
                                              const float* __restrict__ pref) {
    __shared__ __align__(16) float pc[HH2];
    int u = blockIdx.x, tid = threadIdx.x;
    pc[tid] = g_pproj[u*HH2 + tid] + pref[tid];
    __syncthreads();
    int w = tid >> 5, lane = tid & 31;
    for (int s = w; s < SQ; s += 8) {
        int loc = x[s*UBN + u];
        const float4* row = (const float4*)&g_encwP[(size_t)loc*HH2];
        float acc = 0.f;
        #pragma unroll
        for (int q = 0; q < 2; q++) {
            float4 v = row[lane*2 + q];
            float4 p = *(const float4*)&pc[lane*8 + q*4];
            float d0 = p.x - v.x, d1 = p.y - v.y, d2 = p.z - v.z, d3 = p.w - v.w;
            acc += d0*d0 + d1*d1 + d2*d2 + d3*d3;
        }
        #pragma unroll
        for (int o = 16; o > 0; o >>= 1) acc += __shfl_down_sync(0xffffffffu, acc, o);
        if (lane == 0) {
            float z = sqrtf(acc + 1e-12f);
            g_sim[u*SQ + s] = 1.f / (1.f + __expf(z));
        }
    }
}

// ---------------- K6b: transpose t/s into [U][S] float layout ----------------
__global__ void k_transp(const int* __restrict__ t, const int* __restrict__ s2) {
    __shared__ float T[3][32][33];
    int u0 = blockIdx.x * 32, s0 = blockIdx.y * 32;
    int tx = threadIdx.x, ty = threadIdx.y;
    int s = s0 + ty, u = u0 + tx;
    T[0][ty][tx] = (float)t[s*UBN + u];
    T[1][ty][tx] = (float)s2[(s*UBN + u)*2 + 0];
    T[2][ty][tx] = (float)s2[(s*UBN + u)*2 + 1];
    __syncthreads();
    int uo = u0 + ty, so = s0 + tx;
    g_tT [uo*SQ + so] = T[0][tx][ty];
    g_sxT[uo*SQ + so] = T[1][tx][ty];
    g_syT[uo*SQ + so] = T[2][tx][ty];
}

// ---------------- K8: fused weights + weighted sum -> fp16 A ----------------
__global__ void __launch_bounds__(128) k_wsum() {
    __shared__ __align__(16) float wsm[8*SQ];   // w[q][j]
    __shared__ float ssum[8];
    const float K1 = 7.2722052166430399e-05f;   // 2*pi/86400
    const float K2 = 1.1574074074074074e-06f;   // 0.1/86400
    int u = blockIdx.x, ig = blockIdx.y, h = threadIdx.x;
    int ibase = ig * 8;

    const float* tT  = &g_tT [u*SQ];
    const float* sxT = &g_sxT[u*SQ];
    const float* syT = &g_syT[u*SQ];
    const float* sim = &g_sim[u*SQ];

    #pragma unroll
    for (int q8 = 0; q8 < 8; q8++) {
        int idx = q8*128 + h;
        int q = idx >> 7, j = idx & 127;
        int i = ibase + q;
        float w = 0.f;
        if (j <= i) {
            float dt = tT[i] - tT[j];
            float dx = sxT[i] - sxT[j];
            float dy = syT[i] - syT[j];
            float ds = sqrtf(dx*dx + dy*dy);
            float a  = (__cosf(dt * K1) + 1.f) * 0.5f * __expf(-dt * K2);
            float b  = __expf(-ds * 0.1f);
            w = (a*b + 1e-10f) * sim[j];
        }
        wsm[idx] = w;
    }
    __syncthreads();
    {
        int wp = h >> 5, lane = h & 31;
        #pragma unroll
        for (int rr = 0; rr < 2; rr++) {
            int q = wp + rr*4;
            float v = wsm[q*SQ + lane] + wsm[q*SQ + lane + 32]
                    + wsm[q*SQ + lane + 64] + wsm[q*SQ + lane + 96];
            #pragma unroll
            for (int o = 16; o > 0; o >>= 1) v += __shfl_down_sync(0xffffffffu, v, o);
            if (lane == 0) ssum[q] = v;
        }
    }
    __syncthreads();

    float acc[8];
    #pragma unroll
    for (int q = 0; q < 8; q++) acc[q] = 0.f;
    int jmax = ibase + 8;
    for (int j = 0; j < jmax; j++) {
        float r = g_rnn[(j*UBN + u)*HD + h];
        #pragma unroll
        for (int q = 0; q < 8; q++) acc[q] += wsm[q*SQ + j] * r;
    }
    #pragma unroll
    for (int q = 0; q < 8; q++) {
        int m = u*SQ + ibase + q;                 // u-major row
        g_Ah[(size_t)m*HD + h] = __float2half_rn(acc[q] / ssum[q]);
    }
}

// ---------------- K9a: pack/transpose Wfc top half -> fp16 ------------------
__global__ void k_packB(const float* __restrict__ Wfc) {
    __shared__ float t[32][33];
    int nx = blockIdx.x*32, ky = blockIdx.y*32;
    int tx = threadIdx.x, ty = threadIdx.y;
    t[ty][tx] = Wfc[(size_t)(ky + ty)*NLOC + nx + tx];
    __syncthreads();
    int n = nx + ty, k = ky + tx;
    g_Bh[(size_t)n*HD + k] = __float2half_rn(t[tx][ty]);
}

// ---------------- K9b: prebias, 16 users/thread, k-unrolled x4 --------------
__global__ void __launch_bounds__(256) k_prebias(const float* __restrict__ Wfc,
                                                 const float* __restrict__ bfc) {
    __shared__ float spu[64*HD];   // 64 users x 128 k
    int tid = threadIdx.x;
    int n  = blockIdx.x*64 + (tid & 63);
    int ub = blockIdx.y*64;
    int ug = tid >> 6;
    for (int q = tid; q < 64*HD; q += 256)
        spu[q] = g_pu[(ub + (q >> 7))*HD + (q & 127)];
    __syncthreads();

    float acc[16];
    #pragma unroll
    for (int i = 0; i < 16; i++) acc[i] = 0.f;
    const float* pu = &spu[ug*16*HD];
    #pragma unroll 2
    for (int k = 0; k < HD; k += 4) {
        float w0 = __ldg(&Wfc[(size_t)(HD + k + 0)*NLOC + n]);
        float w1 = __ldg(&Wfc[(size_t)(HD + k + 1)*NLOC + n]);
        float w2 = __ldg(&Wfc[(size_t)(HD + k + 2)*NLOC + n]);
        float w3 = __ldg(&Wfc[(size_t)(HD + k + 3)*NLOC + n]);
        #pragma unroll
        for (int uu = 0; uu < 16; uu++) {
            const float4 pv = *(const float4*)&pu[uu*HD + k];
            acc[uu] += pv.x*w0 + pv.y*w1 + pv.z*w2 + pv.w*w3;
        }
    }
    float b = bfc[n];
    #pragma unroll
    for (int uu = 0; uu < 16; uu++)
        g_prebias[(size_t)(ub + ug*16 + uu)*NLOC + n] = acc[uu] + b;
}

// ---------------- K10: fp16 mma GEMM, Mtile=128 (1 user), 2 CTAs/SM ---------
// smem: A 32KB | B 32KB | prebias 512B = 65KB
#define FCA_OFF  0
#define FCB_OFF  32768
#define FCPB_OFF 65536
#define FC_SMEM  66048

__global__ void __launch_bounds__(256, 2) k_fc_mma(float* __restrict__ out) {
    char* smc = (char*)sm;
    uint32_t smb = s2u(smc);
    int tid = threadIdx.x, wid = tid >> 5, lane = tid & 31;
    int n0 = blockIdx.x * 128;
    int m0 = blockIdx.y * 128;            // rows u-major: one user per CTA
    int u0 = m0 >> 7;
    int warpM = (wid >> 2) * 64;          // 0, 64
    int warpN = (wid & 3) * 32;           // 0,32,64,96

    float acc[4][4][4];
    #pragma unroll
    for (int i = 0; i < 4; i++)
        #pragma unroll
        for (int j = 0; j < 4; j++)
            #pragma unroll
            for (int q = 0; q < 4; q++) acc[i][j][q] = 0.f;

    // ---- async load A (32KB) ----
    {
        const uint4* src = (const uint4*)g_Ah;
        #pragma unroll
        for (int it = 0; it < 8; it++) {
            int q = it*256 + tid;
            int rowg = q >> 4, c16 = q & 15;
            cpa16(smb + FCA_OFF + swz(rowg, c16*16),
                  &src[(size_t)(m0 + rowg)*16 + c16]);
        }
    }
    // ---- async load B (32KB), zero-fill OOB ----
    {
        const uint4* src = (const uint4*)g_Bh;
        #pragma unroll
        for (int it = 0; it < 8; it++) {
            int q = it*256 + tid;
            int rowg = q >> 4, c16 = q & 15;
            uint32_t d0 = smb + FCB_OFF + swz(rowg, c16*16);
            if (n0 + rowg < NLOC) {
                cpa16(d0, &src[(size_t)(n0 + rowg)*16 + c16]);
            } else {
                uint4 z = make_uint4(0u, 0u, 0u, 0u);
                *(uint4*)(smc + (d0 - smb)) = z;
            }
        }
    }
    // ---- stage prebias for 1 user x 128 cols ----
    {
        float* pb = (float*)(smc + FCPB_OFF);
        if (tid < 128) {
            int col = n0 + tid;
            float v = 0.f;
            if (col < NLOC) v = g_prebias[(size_t)u0*NLOC + col];
            pb[tid] = v;
        }
    }
    cpa_wait();
    __syncthreads();

    uint32_t aRow = warpM + (lane & 15);
    uint32_t aByt = (lane >> 4) * 16;
    uint32_t bRow = warpN + ((lane >> 4) << 3) + (lane & 7);
    uint32_t bByt = ((lane >> 3) & 1) << 4;

    uint32_t aPl = smb + FCA_OFF;
    uint32_t bPl = smb + FCB_OFF;

    #pragma unroll
    for (int kk = 0; kk < 8; kk++) {
        uint32_t bb[8];
        ldsm4(bb[0], bb[1], bb[2], bb[3], bPl + swz(bRow,      kk*32 + bByt));
        ldsm4(bb[4], bb[5], bb[6], bb[7], bPl + swz(bRow + 16, kk*32 + bByt));
        #pragma unroll
        for (int mt = 0; mt < 4; mt++) {
            uint32_t a[4];
            ldsm4(a[0], a[1], a[2], a[3], aPl + swz(aRow + mt*16, kk*32 + aByt));
            #pragma unroll
            for (int nt = 0; nt < 4; nt++) mma_f16(acc[mt][nt], a, &bb[nt*2]);
        }
    }

    // ---- epilogue: streaming stores (output never re-read) ----
    const float* pb = (const float*)(smc + FCPB_OFF);
    #pragma unroll
    for (int mt = 0; mt < 4; mt++) {
        int i = warpM + mt*16 + (lane >> 2);
        size_t row0 = (size_t)(i*UBN + u0)*NLOC;
        size_t row1 = (size_t)((i + 8)*UBN + u0)*NLOC;
        #pragma unroll
        for (int nt = 0; nt < 4; nt++) {
            int cloc = warpN + nt*8 + (lane & 3)*2;
            int col  = n0 + cloc;
            if (col < NLOC) {
                float2 pbv = *(const float2*)&pb[cloc];
                stg_cs8(&out[row0 + col],
                        make_float2(acc[mt][nt][0] + pbv.x, acc[mt][nt][1] + pbv.y));
                stg_cs8(&out[row1 + col],
                        make_float2(acc[mt][nt][2] + pbv.x, acc[mt][nt][3] + pbv.y));
            }
        }
    }
}

// ---------------- launch ------------------------------------------------------
extern "C" void kernel_launch(void* const* d_in, const int* in_sizes, int n_in,
                              void* d_out, int out_size) {
    const int*   x        = (const int*)  d_in[0];
    const int*   t        = (const int*)  d_in[1];
    const int*   s2       = (const int*)  d_in[3];
    const float* h0       = (const float*)d_in[7];
    const int*   au       = (const int*)  d_in[8];
    const int*   ecols    = (const int*)  d_in[10];
    const float* evals    = (const float*)d_in[11];
    const float* loc_emb  = (const float*)d_in[12];
    const float* user_emb = (const float*)d_in[13];
    const float* pref     = (const float*)d_in[14];
    const float* W_proj   = (const float*)d_in[15];
    const float* b_proj   = (const float*)d_in[16];
    const float* W_gconv  = (const float*)d_in[17];
    const float* b_gconv  = (const float*)d_in[18];
    const float* W_ih     = (const float*)d_in[19];
    const float* W_hh     = (const float*)d_in[20];
    const float* b_ih     = (const float*)d_in[21];
    const float* b_hh     = (const float*)d_in[22];
    const float* W_fc     = (const float*)d_in[23];
    const float* b_fc     = (const float*)d_in[24];
    float* out = (float*)d_out;

    cudaFuncSetAttribute(k_fc_mma, cudaFuncAttributeMaxDynamicSharedMemorySize, FC_SMEM);

    k_init<<<GB_GATHER + HD + 1, 384>>>(ecols, evals, loc_emb, W_gconv, W_ih,
                                        W_proj, b_gconv, b_ih, b_hh, b_proj);
    k_packB<<<dim3(NLOC/32, HD/32), dim3(32, 32)>>>(W_fc);
    k_pproj<<<UBN, HH2>>>(au, user_emb, W_proj, b_proj);
    k_prebias<<<dim3(NLOC/64, UBN/64), 256>>>(W_fc, b_fc);
    k_transp<<<dim3(UBN/32, SQ/32), dim3(32, 32)>>>(t, s2);
    k_tabfused<<<NLOC/16, 384>>>();
    k_rnn2<<<UBN/2, HD>>>(x, W_hh, h0, out);
    k_sim2<<<UBN, 256>>>(x, pref);
    k_wsum<<<dim3(UBN, SQ/8), HD>>>();
    k_fc_mma<<<dim3((NLOC + 127)/128, SQ*UBN/128), 256, FC_SMEM>>>(out);
}